// round 12
// baseline (speedup 1.0000x reference)
#include <cuda_runtime.h>
#include <cuda_bf16.h>
#include <math.h>
#include <stdint.h>

#define Bb 8
#define Nn 1024
#define Ee 256
#define Hh 4
#define Uu 6
#define Oo 8
#define LAMBDA_INIT 0.63212055882855767840f
#define LOG2E 1.44269504088896340736f

typedef unsigned long long ull;

// ---------------- scratch (static device memory; no allocation) ----------------
__device__ unsigned char g_maskT[(size_t)Bb * Nn * Nn];
__device__ __nv_bfloat16 g_v_hi[(size_t)Bb * Nn * Ee];
__device__ __nv_bfloat16 g_v_lo[(size_t)Bb * Nn * Ee];
__device__ __nv_bfloat16 g_x_hi[(size_t)Bb * Nn * Ee];
__device__ __nv_bfloat16 g_x_lo[(size_t)Bb * Nn * Ee];
__device__ __nv_bfloat16 g_op_hi[(size_t)Bb * Nn * Ee];
__device__ __nv_bfloat16 g_op_lo[(size_t)Bb * Nn * Ee];
__device__ __nv_bfloat16 g_vw_hi[(size_t)Ee * Ee];
__device__ __nv_bfloat16 g_vw_lo[(size_t)Ee * Ee];
__device__ __nv_bfloat16 g_ow_hi[(size_t)Ee * Ee];
__device__ __nv_bfloat16 g_ow_lo[(size_t)Ee * Ee];
__device__ float g_l[(size_t)Bb * Oo * Nn];
__device__ float g_beta;
__device__ int   g_mask_kind;

// ---------------- helpers ----------------
__device__ __forceinline__ ull pack2(float a, float b) {
    ull r; asm("mov.b64 %0, {%1,%2};" : "=l"(r) : "f"(a), "f"(b)); return r;
}
__device__ __forceinline__ ull pack2u(uint32_t a, uint32_t b) {
    ull r; asm("mov.b64 %0, {%1,%2};" : "=l"(r) : "r"(a), "r"(b)); return r;
}
__device__ __forceinline__ float2 unpack2(ull v) {
    float2 r; asm("mov.b64 {%0,%1}, %2;" : "=f"(r.x), "=f"(r.y) : "l"(v)); return r;
}
__device__ __forceinline__ ull ffma2(ull a, ull b, ull c) {
    ull d; asm("fma.rn.f32x2 %0, %1, %2, %3;" : "=l"(d) : "l"(a), "l"(b), "l"(c)); return d;
}
__device__ __forceinline__ uint32_t cvt_bf16x2(float a1, float a0) {
    uint32_t r; asm("cvt.rn.bf16x2.f32 %0, %1, %2;" : "=r"(r) : "f"(a1), "f"(a0)); return r;
}
__device__ __forceinline__ float ex2f(float x) {
    float r; asm("ex2.approx.f32 %0, %1;" : "=f"(r) : "f"(x)); return r;
}
__device__ __forceinline__ uint32_t smem_u32(const void* p) {
    uint32_t a;
    asm("{ .reg .u64 t; cvta.to.shared.u64 t, %1; cvt.u32.u64 %0, t; }" : "=r"(a) : "l"(p));
    return a;
}
__device__ __forceinline__ void cp_async16(uint32_t smem_addr, const void* gmem) {
    asm volatile("cp.async.cg.shared.global [%0], [%1], 16;" :: "r"(smem_addr), "l"(gmem));
}
__device__ __forceinline__ void cp_async_commit() {
    asm volatile("cp.async.commit_group;" ::: "memory");
}
__device__ __forceinline__ void cp_async_wait0() {
    asm volatile("cp.async.wait_group 0;" ::: "memory");
}
__device__ __forceinline__ void ldmatrix_x4(uint32_t& r0, uint32_t& r1, uint32_t& r2,
                                            uint32_t& r3, uint32_t addr) {
    asm volatile("ldmatrix.sync.aligned.m8n8.x4.shared.b16 {%0,%1,%2,%3}, [%4];"
                 : "=r"(r0), "=r"(r1), "=r"(r2), "=r"(r3) : "r"(addr));
}
__device__ __forceinline__ void ldmatrix_x4_trans(uint32_t& r0, uint32_t& r1, uint32_t& r2,
                                                  uint32_t& r3, uint32_t addr) {
    asm volatile("ldmatrix.sync.aligned.m8n8.x4.trans.shared.b16 {%0,%1,%2,%3}, [%4];"
                 : "=r"(r0), "=r"(r1), "=r"(r2), "=r"(r3) : "r"(addr));
}
__device__ __forceinline__ void mma_bf16(float* c, uint32_t a0, uint32_t a1, uint32_t a2,
                                         uint32_t a3, uint32_t b0, uint32_t b1) {
    asm volatile(
        "mma.sync.aligned.m16n8k16.row.col.f32.bf16.bf16.f32 "
        "{%0,%1,%2,%3}, {%4,%5,%6,%7}, {%8,%9}, {%0,%1,%2,%3};"
        : "+f"(c[0]), "+f"(c[1]), "+f"(c[2]), "+f"(c[3])
        : "r"(a0), "r"(a1), "r"(a2), "r"(a3), "r"(b0), "r"(b1));
}

// ---------------- L1: detect mask dtype + beta ----------------
__global__ void detect_beta_kernel(const unsigned char* __restrict__ raw,
                                   const float* __restrict__ lq,
                                   const float* __restrict__ lk,
                                   float* __restrict__ beta_slot) {
    __shared__ int cnt[4];
    __shared__ float red[128];
    int t = threadIdx.x;
    if (t < 4) cnt[t] = 0;
    if (t < 128) red[t] = (t < 100) ? lq[t] * lk[t] : 0.f;
    __syncthreads();
    for (int i = t; i < 16384; i += blockDim.x)
        if (raw[i]) atomicAdd(&cnt[i & 3], 1);
    for (int st = 64; st > 0; st >>= 1) {
        if (t < st) red[t] += red[t + st];
        __syncthreads();
    }
    if (t == 0) {
        int kind;
        if (cnt[1] == 0 && cnt[2] == 0 && cnt[3] == 0) kind = 1;
        else if (cnt[0] == 0 && cnt[1] == 0)           kind = 2;
        else                                            kind = 0;
        g_mask_kind = kind;
        float lam1 = expf(red[0]);
        float beta = 1.f / (1.f + expf(-lam1 * LAMBDA_INIT));
        g_beta = beta;
        *beta_slot = beta;
    }
}

// ---------------- L2: prep = mask transpose + splits ----------------
#define NX4 ((int)((size_t)Bb * Nn * Ee / 4))
#define NW4 (Ee * Ee / 4)
#define PREP_GRID (8192 + (NX4 + 2 * NW4) / 256)

__global__ __launch_bounds__(256) void prep_kernel(const void* __restrict__ rawv,
                                                   const float* __restrict__ x,
                                                   const float* __restrict__ vw,
                                                   const float* __restrict__ ow) {
    int bid = blockIdx.x;
    if (bid < 8192) {
        __shared__ unsigned char tile[32][33];
        int xt = bid & 31, yt = (bid >> 5) & 31, b = bid >> 10;
        int i0 = xt * 32, j0 = yt * 32;
        int tx = threadIdx.x & 31, ty0 = threadIdx.x >> 5;
        int kind = g_mask_kind;
#pragma unroll
        for (int k = 0; k < 4; k++) {
            int ty = ty0 + k * 8;
            size_t src = ((size_t)b * Nn + (j0 + ty)) * Nn + (i0 + tx);
            unsigned char v;
            if (kind == 0)      v = (((const unsigned char*)rawv)[src] != 0);
            else if (kind == 1) v = (((const int*)rawv)[src] != 0);
            else                v = (((const float*)rawv)[src] != 0.f);
            tile[ty][tx] = v;
        }
        __syncthreads();
#pragma unroll
        for (int k = 0; k < 4; k++) {
            int ty = ty0 + k * 8;
            g_maskT[((size_t)b * Nn + (i0 + ty)) * Nn + (j0 + tx)] = tile[tx][ty];
        }
    } else {
        int idx = (bid - 8192) * 256 + threadIdx.x;
        const float* src;
        uint2 *hid, *lod;
        int li;
        if (idx < NX4) {
            src = x; hid = (uint2*)g_x_hi; lod = (uint2*)g_x_lo; li = idx;
        } else if (idx < NX4 + NW4) {
            src = vw; hid = (uint2*)g_vw_hi; lod = (uint2*)g_vw_lo; li = idx - NX4;
        } else {
            src = ow; hid = (uint2*)g_ow_hi; lod = (uint2*)g_ow_lo; li = idx - NX4 - NW4;
        }
        float4 v = ((const float4*)src)[li];
        uint32_t h0 = cvt_bf16x2(v.y, v.x);
        uint32_t h1 = cvt_bf16x2(v.w, v.z);
        float a0 = __uint_as_float(h0 << 16), a1 = __uint_as_float(h0 & 0xFFFF0000u);
        float a2 = __uint_as_float(h1 << 16), a3 = __uint_as_float(h1 & 0xFFFF0000u);
        uint32_t l0 = cvt_bf16x2(v.y - a1, v.x - a0);
        uint32_t l1 = cvt_bf16x2(v.w - a3, v.z - a2);
        hid[li] = make_uint2(h0, h1);
        lod[li] = make_uint2(l0, l1);
    }
}

// ---------------- gemm body (HMMA, 64x64 tile, 3 hi/lo combos) ----------------
#define GR_STR 144
#define GEMM_SMEM (4 * 64 * GR_STR)
template <int MODE>
__device__ __forceinline__ void gemm_body(
    char* sm, int bx, int by,
    const __nv_bfloat16* __restrict__ Ahi, const __nv_bfloat16* __restrict__ Alo,
    const __nv_bfloat16* __restrict__ Whi, const __nv_bfloat16* __restrict__ Wlo,
    float* __restrict__ Y, __nv_bfloat16* __restrict__ Yhi, __nv_bfloat16* __restrict__ Ylo) {
    char* sAh = sm;
    char* sAl = sm + 64 * GR_STR;
    char* sWh = sm + 2 * 64 * GR_STR;
    char* sWl = sm + 3 * 64 * GR_STR;
    const uint32_t smb = smem_u32(sm);

    const int t = threadIdx.x;
    const int wid = t >> 5, lane = t & 31;
    const int row0 = bx * 64;
    const int col0 = by * 64;
    const int mw = wid >> 1, nw = wid & 1;
    const int lr = lane & 7, quad = lane >> 3;
    const uint32_t aRow = (uint32_t)(mw * 16 + (quad & 1) * 8 + lr);
    const uint32_t aKoff = (uint32_t)((quad >> 1) * 16);
    const uint32_t bRow = (uint32_t)((quad >> 1) * 8 + lr);
    const uint32_t bKoff = (uint32_t)((quad & 1) * 16);

    float c[4][4];
#pragma unroll
    for (int nf = 0; nf < 4; nf++)
#pragma unroll
        for (int k = 0; k < 4; k++) c[nf][k] = 0.f;

    for (int kc = 0; kc < 4; kc++) {
        __syncthreads();
#pragma unroll
        for (int q = 0; q < 2; q++) {
            int idx = t + q * 256;
            int r = idx >> 3, c16 = idx & 7;
            *(uint4*)(sAh + r * GR_STR + c16 * 16) =
                ((const uint4*)(Ahi + (size_t)(row0 + r) * Ee + kc * 64))[c16];
            *(uint4*)(sAl + r * GR_STR + c16 * 16) =
                ((const uint4*)(Alo + (size_t)(row0 + r) * Ee + kc * 64))[c16];
            *(uint4*)(sWh + r * GR_STR + c16 * 16) =
                ((const uint4*)(Whi + (size_t)(col0 + r) * Ee + kc * 64))[c16];
            *(uint4*)(sWl + r * GR_STR + c16 * 16) =
                ((const uint4*)(Wlo + (size_t)(col0 + r) * Ee + kc * 64))[c16];
        }
        __syncthreads();
#pragma unroll
        for (int ks = 0; ks < 4; ks++) {
            uint32_t aBase = smb + aRow * GR_STR + ks * 32 + aKoff;
            uint32_t ah0, ah1, ah2, ah3, al0, al1, al2, al3;
            ldmatrix_x4(ah0, ah1, ah2, ah3, aBase);
            ldmatrix_x4(al0, al1, al2, al3, aBase + 64 * GR_STR);
#pragma unroll
            for (int np = 0; np < 2; np++) {
                uint32_t bBase = smb + 2 * 64 * GR_STR +
                                 (nw * 32 + np * 16 + bRow) * GR_STR + ks * 32 + bKoff;
                uint32_t bh0, bh1, bh2, bh3, bl0, bl1, bl2, bl3;
                ldmatrix_x4(bh0, bh1, bh2, bh3, bBase);
                ldmatrix_x4(bl0, bl1, bl2, bl3, bBase + 64 * GR_STR);
                float* c0 = c[np * 2];
                float* c1 = c[np * 2 + 1];
                mma_bf16(c0, ah0, ah1, ah2, ah3, bh0, bh1);
                mma_bf16(c0, ah0, ah1, ah2, ah3, bl0, bl1);
                mma_bf16(c0, al0, al1, al2, al3, bh0, bh1);
                mma_bf16(c1, ah0, ah1, ah2, ah3, bh2, bh3);
                mma_bf16(c1, ah0, ah1, ah2, ah3, bl2, bl3);
                mma_bf16(c1, al0, al1, al2, al3, bh2, bh3);
            }
        }
    }

    int r0 = row0 + mw * 16 + (lane >> 2);
    int colb = col0 + nw * 32 + (lane & 3) * 2;
#pragma unroll
    for (int nf = 0; nf < 4; nf++) {
        int col = colb + nf * 8;
        if (MODE == 0) {
            *(float2*)(Y + (size_t)r0 * Ee + col) = make_float2(c[nf][0], c[nf][1]);
            *(float2*)(Y + (size_t)(r0 + 8) * Ee + col) = make_float2(c[nf][2], c[nf][3]);
        } else {
            uint32_t h0 = cvt_bf16x2(c[nf][1], c[nf][0]);
            float e0 = __uint_as_float(h0 << 16), e1 = __uint_as_float(h0 & 0xFFFF0000u);
            uint32_t l0 = cvt_bf16x2(c[nf][1] - e1, c[nf][0] - e0);
            uint32_t h1 = cvt_bf16x2(c[nf][3], c[nf][2]);
            float e2 = __uint_as_float(h1 << 16), e3 = __uint_as_float(h1 & 0xFFFF0000u);
            uint32_t l1 = cvt_bf16x2(c[nf][3] - e3, c[nf][2] - e2);
            ((uint32_t*)Yhi)[((size_t)r0 * Ee + col) >> 1] = h0;
            ((uint32_t*)Ylo)[((size_t)r0 * Ee + col) >> 1] = l0;
            ((uint32_t*)Yhi)[((size_t)(r0 + 8) * Ee + col) >> 1] = h1;
            ((uint32_t*)Ylo)[((size_t)(r0 + 8) * Ee + col) >> 1] = l1;
        }
    }
}

// ---------------- stats body ----------------
__device__ __forceinline__ void stats_body(char* sm, int i, int b,
                                           const float* __restrict__ u,
                                           const float* __restrict__ u_w,
                                           const float* __restrict__ u_b) {
    ull* s_w2 = (ull*)sm;
    ull* s_b2 = (ull*)(sm + 384);
    float* s_red = (float*)(sm + 448);
    int t = threadIdx.x;
    if (t < 48) { float w = u_w[t] * LOG2E; s_w2[t] = pack2(w, w); }
    if (t < 8)  { float bb = u_b[t] * LOG2E; s_b2[t] = pack2(bb, bb); }
    __syncthreads();

    int j0 = t * 4;
    unsigned mword = *(const unsigned*)(g_maskT + ((size_t)b * Nn + i) * Nn + j0);
    bool m0 = (mword & 0xFFu) != 0, m1 = ((mword >> 8) & 0xFFu) != 0;
    bool m2 = ((mword >> 16) & 0xFFu) != 0, m3 = ((mword >> 24) & 0xFFu) != 0;

    ulonglong2 u2[Uu];
#pragma unroll
    for (int c = 0; c < Uu; c++)
        u2[c] = *(const ulonglong2*)(u + ((size_t)(b * Uu + c) * Nn + i) * Nn + j0);

    float l[Oo];
#pragma unroll
    for (int o = 0; o < Oo; o++) {
        ull sa = s_b2[o], sb = s_b2[o];
#pragma unroll
        for (int c = 0; c < Uu; c++) {
            sa = ffma2(s_w2[o * Uu + c], u2[c].x, sa);
            sb = ffma2(s_w2[o * Uu + c], u2[c].y, sb);
        }
        float2 f0 = unpack2(sa), f1 = unpack2(sb);
        float acc = 0.f;
        if (!m0) acc += ex2f(f0.x);
        if (!m1) acc += ex2f(f0.y);
        if (!m2) acc += ex2f(f1.x);
        if (!m3) acc += ex2f(f1.y);
        l[o] = acc;
    }
#pragma unroll
    for (int o = 0; o < Oo; o++)
#pragma unroll
        for (int st = 16; st > 0; st >>= 1)
            l[o] += __shfl_xor_sync(0xFFFFFFFFu, l[o], st);
    int w = t >> 5, lane = t & 31;
    if (lane == 0) {
#pragma unroll
        for (int o = 0; o < Oo; o++) s_red[o * 9 + w] = l[o];
    }
    __syncthreads();
    if (t < 8) {
        float s = 0.f;
#pragma unroll
        for (int w2 = 0; w2 < 8; w2++) s += s_red[t * 9 + w2];
        g_l[((size_t)b * Oo + t) * Nn + i] = s;
    }
}

// ---------------- L3: gemm<1> + stats ----------------
__global__ __launch_bounds__(256) void gemm1_stats_kernel(const float* __restrict__ u,
                                                          const float* __restrict__ u_w,
                                                          const float* __restrict__ u_b) {
    __shared__ __align__(16) char sm[GEMM_SMEM];
    int bid = blockIdx.x;
    if (bid < 512) {
        gemm_body<1>(sm, bid & 127, bid >> 7,
                     g_x_hi, g_x_lo, g_vw_hi, g_vw_lo, nullptr, g_v_hi, g_v_lo);
    } else {
        int sid = bid - 512;
        stats_body(sm, sid & 1023, sid >> 10, u, u_w, u_b);
    }
}

// ---------------- L5: out projection ----------------
__global__ __launch_bounds__(256) void gemm0_kernel(float* __restrict__ Y) {
    __shared__ __align__(16) char sm[GEMM_SMEM];
    gemm_body<0>(sm, blockIdx.x, blockIdx.y,
                 g_op_hi, g_op_lo, g_ow_hi, g_ow_lo, Y, nullptr, nullptr);
}

// ---------------- L4: fused — R10 geometry + unroll2 + incremental attn pointers ----------------
#define SB_W2    0
#define SB_B2    384
#define SB_BETA  448
#define SB_RL    464
#define SB_BUF0  2560
#define A_HSTR   9216        // 64 rows x 144
#define A_RSTR   144
#define V_RSTR   528
#define BA_OFF   0
#define BVH_OFF  36864       // A = 4*9216
#define BVL_OFF  53760       // +32*528
#define BUF_STR  70656       // +32*528
#define SB_TOT   (2560 + 2 * 70656)   // 143872

__global__ __launch_bounds__(512, 1) void fused_kernel(const float* __restrict__ u,
                                                       const float* __restrict__ u_w,
                                                       const float* __restrict__ u_b,
                                                       float* __restrict__ attn_out) {
    extern __shared__ char smc[];
    const uint32_t smem_base = smem_u32(smc);
    ull*   s_w2   = (ull*)(smc + SB_W2);
    ull*   s_b2   = (ull*)(smc + SB_B2);
    float* s_beta = (float*)(smc + SB_BETA);
    float* s_rl   = (float*)(smc + SB_RL);

    const int t = threadIdx.x;
    const int wid = t >> 5;
    const int lane = t & 31;
    const int b = blockIdx.y;
    const int i0 = blockIdx.x * 64;

    if (t < 48)      { float w = u_w[t] * LOG2E; s_w2[t] = pack2(w, w); }
    else if (t < 56) { float bb = u_b[t - 48] * LOG2E; s_b2[t - 48] = pack2(bb, bb); }
    else if (t == 56) *s_beta = g_beta;
    {
        int o = t >> 6, il2 = t & 63;
        s_rl[t] = 1.0f / g_l[((size_t)b * Oo + o) * Nn + i0 + il2];
    }
    __syncthreads();

    const float beta = *s_beta;
    // phase A mapping: 1 row x 4 j per thread (64 rows x 8 jq)
    const int jq = t & 7;
    const int il = t >> 3;
    const int gi = i0 + il;
    // phase B mapping: warp -> (head, 16-row group)
    const int h_b = wid >> 2;
    const int ig = wid & 3;
    const int lg = lane >> 3, lr = lane & 7;
    const uint32_t a_lm_row = (uint32_t)(ig * 16 + (lg & 1) * 8 + lr);
    const uint32_t a_lm_kh = (uint32_t)(lg >> 1);
    const uint32_t b_lm_krow = (uint32_t)((lg & 1) * 8 + lr);
    const uint32_t b_lm_ncol = (uint32_t)(h_b * 64 + (lg >> 1) * 8);

    float rl[Oo];
#pragma unroll
    for (int o = 0; o < Oo; o++) rl[o] = s_rl[o * 64 + il];

    // incremental attn store pointers: a01 covers h=0,1 (offsets 0, 4MB); a23 covers h=2,3
    float* attn01 = attn_out + ((size_t)(b * Hh) * Nn + gi) * Nn + jq * 4;
    float* attn23 = attn01 + 2 * (size_t)Nn * Nn;

    float c[8][4];
#pragma unroll
    for (int nf = 0; nf < 8; nf++)
#pragma unroll
        for (int k = 0; k < 4; k++) c[nf][k] = 0.f;

    // V tile cp.async: 2048 chunks of 16B / 512 thr = 4 each
    auto cp_v = [&](int jt, uint32_t buf_sm) {
#pragma unroll
        for (int q = 0; q < 4; q++) {
            int cidx = t + q * 512;
            int isLo = cidx >> 10;
            int r = (cidx >> 5) & 31;
            int k16 = cidx & 31;
            const __nv_bfloat16* src = (isLo ? g_v_lo : g_v_hi) +
                ((size_t)b * Nn + jt * 32 + r) * Ee + k16 * 8;
            cp_async16(buf_sm + (isLo ? BVL_OFF : BVH_OFF) + r * V_RSTR + k16 * 16, src);
        }
        cp_async_commit();
    };

    auto load_u = [&](int jg0, ulonglong2* u2, unsigned& mw) {
        mw = __ldcs((const unsigned*)(g_maskT + ((size_t)b * Nn + gi) * Nn + jg0));
#pragma unroll
        for (int cc = 0; cc < Uu; cc++) {
            uint4 raw = __ldcs((const uint4*)(u + ((size_t)(b * Uu + cc) * Nn + gi) * Nn + jg0));
            u2[cc].x = pack2u(raw.x, raw.y);
            u2[cc].y = pack2u(raw.z, raw.w);
        }
    };

    // phase A: compute scores, write attn via incremental pointers, STS bf16 hi/lo A
    auto phaseA = [&](char* buf, const ulonglong2* u2, unsigned mword,
                      float* a01, float* a23) {
        bool m0 = (mword & 0xFFu) != 0, m1 = ((mword >> 8) & 0xFFu) != 0;
        bool m2 = ((mword >> 16) & 0xFFu) != 0, m3 = ((mword >> 24) & 0xFFu) != 0;
        const uint32_t abyte = (uint32_t)(il * A_RSTR + jq * 8);
#pragma unroll
        for (int h = 0; h < Hh; h++) {
            int o0 = 2 * h, o1 = 2 * h + 1;
            ull sa0 = s_b2[o0], sb0 = s_b2[o0];
            ull sa1 = s_b2[o1], sb1 = s_b2[o1];
#pragma unroll
            for (int cc = 0; cc < Uu; cc++) {
                sa0 = ffma2(s_w2[o0 * Uu + cc], u2[cc].x, sa0);
                sb0 = ffma2(s_w2[o0 * Uu + cc], u2[cc].y, sb0);
                sa1 = ffma2(s_w2[o1 * Uu + cc], u2[cc].x, sa1);
                sb1 = ffma2(s_w2[o1 * Uu + cc], u2[cc].y, sb1);
            }
            float2 f00 = unpack2(sa0), f01 = unpack2(sb0);
            float2 f10 = unpack2(sa1), f11 = unpack2(sb1);
            float p00 = m0 ? 0.f : ex2f(f00.x) * rl[o0];
            float p01 = m1 ? 0.f : ex2f(f00.y) * rl[o0];
            float p02 = m2 ? 0.f : ex2f(f01.x) * rl[o0];
            float p03 = m3 ? 0.f : ex2f(f01.y) * rl[o0];
            float p10 = m0 ? 0.f : ex2f(f10.x) * rl[o1];
            float p11 = m1 ? 0.f : ex2f(f10.y) * rl[o1];
            float p12 = m2 ? 0.f : ex2f(f11.x) * rl[o1];
            float p13 = m3 ? 0.f : ex2f(f11.y) * rl[o1];
            float a0 = p00 - beta * p10;
            float a1 = p01 - beta * p11;
            float a2 = p02 - beta * p12;
            float a3 = p03 - beta * p13;
            float* dst = (h < 2) ? (a01 + (h & 1) * ((size_t)Nn * Nn))
                                 : (a23 + (h & 1) * ((size_t)Nn * Nn));
            __stcs((float4*)dst, make_float4(a0, a1, a2, a3));
            uint32_t hA = cvt_bf16x2(a1, a0);
            uint32_t hB = cvt_bf16x2(a3, a2);
            float e0 = __uint_as_float(hA << 16);
            float e1 = __uint_as_float(hA & 0xFFFF0000u);
            float e2 = __uint_as_float(hB << 16);
            float e3 = __uint_as_float(hB & 0xFFFF0000u);
            uint32_t lA = cvt_bf16x2(a1 - e1, a0 - e0);
            uint32_t lB = cvt_bf16x2(a3 - e3, a2 - e2);
            char* ap = buf + BA_OFF + h * A_HSTR + abyte;
            *(uint2*)(ap)      = make_uint2(hA, hB);
            *(uint2*)(ap + 64) = make_uint2(lA, lB);
        }
    };

    // ---- prologue: tile 0 ----
    {
        char* buf0 = smc + SB_BUF0;
        cp_v(0, smem_base + SB_BUF0);
        ulonglong2 u2[Uu];
        unsigned mw;
        load_u(jq * 4, u2, mw);
        phaseA(buf0, u2, mw, attn01, attn23);
        cp_async_wait0();
        __syncthreads();
    }

    // ---- pipelined main loop (32 tiles of 32 j), unroll 2 for compile-time parity ----
#pragma unroll 2
    for (int jt = 0; jt < 32; jt++) {
        char* bufN = smc + SB_BUF0 + ((jt + 1) & 1) * BUF_STR;
        const uint32_t bufN_sm = smem_base + SB_BUF0 + ((jt + 1) & 1) * BUF_STR;
        const uint32_t bufC_sm = smem_base + SB_BUF0 + (jt & 1) * BUF_STR;
        const bool has_next = (jt < 31);

        ulonglong2 u2[Uu];
        unsigned mw = 0;
        if (has_next) {
            cp_v(jt + 1, bufN_sm);
            load_u((jt + 1) * 32 + jq * 4, u2, mw);
        }

        // phase B: MMA from current buffer
#pragma unroll
        for (int ks = 0; ks < 2; ks++) {
            uint32_t aAddr = bufC_sm + BA_OFF + h_b * A_HSTR + a_lm_row * A_RSTR +
                             ks * 32 + a_lm_kh * 16;
            uint32_t ah0, ah1, ah2, ah3, al0, al1, al2, al3;
            ldmatrix_x4(ah0, ah1, ah2, ah3, aAddr);
            ldmatrix_x4(al0, al1, al2, al3, aAddr + 64);
#pragma unroll
            for (int np = 0; np < 4; np++) {
                uint32_t bAddr = bufC_sm + BVH_OFF +
                                 (ks * 16 + b_lm_krow) * V_RSTR +
                                 (b_lm_ncol + np * 16) * 2;
                uint32_t bh0, bh1, bh2, bh3, bl0, bl1, bl2, bl3;
                ldmatrix_x4_trans(bh0, bh1, bh2, bh3, bAddr);
                ldmatrix_x4_trans(bl0, bl1, bl2, bl3, bAddr + (BVL_OFF - BVH_OFF));
                float* c0 = c[np * 2];
                float* c1 = c[np * 2 + 1];
                mma_bf16(c0, ah0, ah1, ah2, ah3, bh0, bh1);
                mma_bf16(c0, ah0, ah1, ah2, ah3, bl0, bl1);
                mma_bf16(c0, al0, al1, al2, al3, bh0, bh1);
                mma_bf16(c1, ah0, ah1, ah2, ah3, bh2, bh3);
                mma_bf16(c1, ah0, ah1, ah2, ah3, bl2, bl3);
                mma_bf16(c1, al0, al1, al2, al3, bh2, bh3);
            }
        }

        if (has_next) {
            attn01 += 32;
            attn23 += 32;
            phaseA(bufN, u2, mw, attn01, attn23);
            cp_async_wait0();
        }
        __syncthreads();
    }

    // ---- epilogue ----
    {
        int r = lane >> 2, cq = lane & 3;
        int go0 = i0 + ig * 16 + r;
        int go1 = go0 + 8;
#pragma unroll
        for (int nf = 0; nf < 8; nf++) {
            int col = h_b * 64 + nf * 8 + cq * 2;
            uint32_t h0 = cvt_bf16x2(c[nf][1], c[nf][0]);
            float e0 = __uint_as_float(h0 << 16), e1 = __uint_as_float(h0 & 0xFFFF0000u);
            uint32_t l0 = cvt_bf16x2(c[nf][1] - e1, c[nf][0] - e0);
            uint32_t h1 = cvt_bf16x2(c[nf][3], c[nf][2]);
            float e2 = __uint_as_float(h1 << 16), e3 = __uint_as_float(h1 & 0xFFFF0000u);
            uint32_t l1 = cvt_bf16x2(c[nf][3] - e3, c[nf][2] - e2);
            ((uint32_t*)g_op_hi)[(((size_t)b * Nn + go0) * Ee + col) >> 1] = h0;
            ((uint32_t*)g_op_lo)[(((size_t)b * Nn + go0) * Ee + col) >> 1] = l0;
            ((uint32_t*)g_op_hi)[(((size_t)b * Nn + go1) * Ee + col) >> 1] = h1;
            ((uint32_t*)g_op_lo)[(((size_t)b * Nn + go1) * Ee + col) >> 1] = l1;
        }
    }
}

// ---------------- launch ----------------
extern "C" void kernel_launch(void* const* d_in, const int* in_sizes, int n_in,
                              void* d_out, int out_size) {
    const float* x     = (const float*)d_in[0];
    const float* u     = (const float*)d_in[1];
    const void*  umask = d_in[2];
    const float* v_w   = (const float*)d_in[3];
    const float* out_w = (const float*)d_in[4];
    const float* u_w   = (const float*)d_in[5];
    const float* u_b   = (const float*)d_in[6];
    const float* lq    = (const float*)d_in[7];
    const float* lk    = (const float*)d_in[8];

    float* out = (float*)d_out;
    const size_t OUT_ELEMS  = (size_t)Bb * Nn * Ee;
    const size_t ATTN_ELEMS = (size_t)Bb * Hh * Nn * Nn;
    float* attn_out  = out + OUT_ELEMS;
    float* beta_slot = out + OUT_ELEMS + ATTN_ELEMS;

    static bool attr_set = false;
    if (!attr_set) {
        cudaFuncSetAttribute(fused_kernel, cudaFuncAttributeMaxDynamicSharedMemorySize, SB_TOT);
        attr_set = true;
    }

    detect_beta_kernel<<<1, 256>>>((const unsigned char*)umask, lq, lk, beta_slot);  // #1
    prep_kernel<<<PREP_GRID, 256>>>(umask, x, v_w, out_w);                            // #2
    gemm1_stats_kernel<<<512 + Nn * Bb, 256>>>(u, u_w, u_b);                          // #3
    fused_kernel<<<dim3(16, 8), 512, SB_TOT>>>(u, u_w, u_b, attn_out);                // #4 (profiled)
    gemm0_kernel<<<dim3(128, 4), 256>>>(out);                                         // #5
    (void)in_sizes; (void)n_in; (void)out_size;
}

// round 13
// speedup vs baseline: 1.0989x; 1.0989x over previous
#include <cuda_runtime.h>
#include <cuda_bf16.h>
#include <math.h>
#include <stdint.h>

#define Bb 8
#define Nn 1024
#define Ee 256
#define Hh 4
#define Uu 6
#define Oo 8
#define LAMBDA_INIT 0.63212055882855767840f
#define LOG2E 1.44269504088896340736f

typedef unsigned long long ull;

// ---------------- scratch (static device memory; no allocation) ----------------
__device__ unsigned char g_maskT[(size_t)Bb * Nn * Nn];
__device__ __nv_bfloat16 g_v_hi[(size_t)Bb * Nn * Ee];
__device__ __nv_bfloat16 g_v_lo[(size_t)Bb * Nn * Ee];
__device__ __nv_bfloat16 g_x_hi[(size_t)Bb * Nn * Ee];
__device__ __nv_bfloat16 g_x_lo[(size_t)Bb * Nn * Ee];
__device__ __nv_bfloat16 g_op_hi[(size_t)Bb * Nn * Ee];
__device__ __nv_bfloat16 g_op_lo[(size_t)Bb * Nn * Ee];
__device__ __nv_bfloat16 g_vw_hi[(size_t)Ee * Ee];
__device__ __nv_bfloat16 g_vw_lo[(size_t)Ee * Ee];
__device__ __nv_bfloat16 g_ow_hi[(size_t)Ee * Ee];
__device__ __nv_bfloat16 g_ow_lo[(size_t)Ee * Ee];
__device__ float g_l[(size_t)Bb * Oo * Nn];
__device__ float g_beta;
__device__ int   g_mask_kind;

// ---------------- helpers ----------------
__device__ __forceinline__ ull pack2(float a, float b) {
    ull r; asm("mov.b64 %0, {%1,%2};" : "=l"(r) : "f"(a), "f"(b)); return r;
}
__device__ __forceinline__ ull pack2u(uint32_t a, uint32_t b) {
    ull r; asm("mov.b64 %0, {%1,%2};" : "=l"(r) : "r"(a), "r"(b)); return r;
}
__device__ __forceinline__ float2 unpack2(ull v) {
    float2 r; asm("mov.b64 {%0,%1}, %2;" : "=f"(r.x), "=f"(r.y) : "l"(v)); return r;
}
__device__ __forceinline__ ull ffma2(ull a, ull b, ull c) {
    ull d; asm("fma.rn.f32x2 %0, %1, %2, %3;" : "=l"(d) : "l"(a), "l"(b), "l"(c)); return d;
}
__device__ __forceinline__ uint32_t cvt_bf16x2(float a1, float a0) {
    uint32_t r; asm("cvt.rn.bf16x2.f32 %0, %1, %2;" : "=r"(r) : "f"(a1), "f"(a0)); return r;
}
__device__ __forceinline__ float ex2f(float x) {
    float r; asm("ex2.approx.f32 %0, %1;" : "=f"(r) : "f"(x)); return r;
}
__device__ __forceinline__ uint32_t smem_u32(const void* p) {
    uint32_t a;
    asm("{ .reg .u64 t; cvta.to.shared.u64 t, %1; cvt.u32.u64 %0, t; }" : "=r"(a) : "l"(p));
    return a;
}
__device__ __forceinline__ void cp_async16(uint32_t smem_addr, const void* gmem) {
    asm volatile("cp.async.cg.shared.global [%0], [%1], 16;" :: "r"(smem_addr), "l"(gmem));
}
__device__ __forceinline__ void cp_async_commit() {
    asm volatile("cp.async.commit_group;" ::: "memory");
}
__device__ __forceinline__ void cp_async_wait0() {
    asm volatile("cp.async.wait_group 0;" ::: "memory");
}
__device__ __forceinline__ void ldmatrix_x4(uint32_t& r0, uint32_t& r1, uint32_t& r2,
                                            uint32_t& r3, uint32_t addr) {
    asm volatile("ldmatrix.sync.aligned.m8n8.x4.shared.b16 {%0,%1,%2,%3}, [%4];"
                 : "=r"(r0), "=r"(r1), "=r"(r2), "=r"(r3) : "r"(addr));
}
__device__ __forceinline__ void ldmatrix_x4_trans(uint32_t& r0, uint32_t& r1, uint32_t& r2,
                                                  uint32_t& r3, uint32_t addr) {
    asm volatile("ldmatrix.sync.aligned.m8n8.x4.trans.shared.b16 {%0,%1,%2,%3}, [%4];"
                 : "=r"(r0), "=r"(r1), "=r"(r2), "=r"(r3) : "r"(addr));
}
__device__ __forceinline__ void mma_bf16(float* c, uint32_t a0, uint32_t a1, uint32_t a2,
                                         uint32_t a3, uint32_t b0, uint32_t b1) {
    asm volatile(
        "mma.sync.aligned.m16n8k16.row.col.f32.bf16.bf16.f32 "
        "{%0,%1,%2,%3}, {%4,%5,%6,%7}, {%8,%9}, {%0,%1,%2,%3};"
        : "+f"(c[0]), "+f"(c[1]), "+f"(c[2]), "+f"(c[3])
        : "r"(a0), "r"(a1), "r"(a2), "r"(a3), "r"(b0), "r"(b1));
}

// ---------------- L1: detect mask dtype + beta ----------------
__global__ void detect_beta_kernel(const unsigned char* __restrict__ raw,
                                   const float* __restrict__ lq,
                                   const float* __restrict__ lk,
                                   float* __restrict__ beta_slot) {
    __shared__ int cnt[4];
    __shared__ float red[128];
    int t = threadIdx.x;
    if (t < 4) cnt[t] = 0;
    if (t < 128) red[t] = (t < 100) ? lq[t] * lk[t] : 0.f;
    __syncthreads();
    for (int i = t; i < 16384; i += blockDim.x)
        if (raw[i]) atomicAdd(&cnt[i & 3], 1);
    for (int st = 64; st > 0; st >>= 1) {
        if (t < st) red[t] += red[t + st];
        __syncthreads();
    }
    if (t == 0) {
        int kind;
        if (cnt[1] == 0 && cnt[2] == 0 && cnt[3] == 0) kind = 1;
        else if (cnt[0] == 0 && cnt[1] == 0)           kind = 2;
        else                                            kind = 0;
        g_mask_kind = kind;
        float lam1 = expf(red[0]);
        float beta = 1.f / (1.f + expf(-lam1 * LAMBDA_INIT));
        g_beta = beta;
        *beta_slot = beta;
    }
}

// ---------------- L2: prep = mask transpose + splits ----------------
#define NX4 ((int)((size_t)Bb * Nn * Ee / 4))
#define NW4 (Ee * Ee / 4)
#define PREP_GRID (8192 + (NX4 + 2 * NW4) / 256)

__global__ __launch_bounds__(256) void prep_kernel(const void* __restrict__ rawv,
                                                   const float* __restrict__ x,
                                                   const float* __restrict__ vw,
                                                   const float* __restrict__ ow) {
    int bid = blockIdx.x;
    if (bid < 8192) {
        __shared__ unsigned char tile[32][33];
        int xt = bid & 31, yt = (bid >> 5) & 31, b = bid >> 10;
        int i0 = xt * 32, j0 = yt * 32;
        int tx = threadIdx.x & 31, ty0 = threadIdx.x >> 5;
        int kind = g_mask_kind;
#pragma unroll
        for (int k = 0; k < 4; k++) {
            int ty = ty0 + k * 8;
            size_t src = ((size_t)b * Nn + (j0 + ty)) * Nn + (i0 + tx);
            unsigned char v;
            if (kind == 0)      v = (((const unsigned char*)rawv)[src] != 0);
            else if (kind == 1) v = (((const int*)rawv)[src] != 0);
            else                v = (((const float*)rawv)[src] != 0.f);
            tile[ty][tx] = v;
        }
        __syncthreads();
#pragma unroll
        for (int k = 0; k < 4; k++) {
            int ty = ty0 + k * 8;
            g_maskT[((size_t)b * Nn + (i0 + ty)) * Nn + (j0 + tx)] = tile[tx][ty];
        }
    } else {
        int idx = (bid - 8192) * 256 + threadIdx.x;
        const float* src;
        uint2 *hid, *lod;
        int li;
        if (idx < NX4) {
            src = x; hid = (uint2*)g_x_hi; lod = (uint2*)g_x_lo; li = idx;
        } else if (idx < NX4 + NW4) {
            src = vw; hid = (uint2*)g_vw_hi; lod = (uint2*)g_vw_lo; li = idx - NX4;
        } else {
            src = ow; hid = (uint2*)g_ow_hi; lod = (uint2*)g_ow_lo; li = idx - NX4 - NW4;
        }
        float4 v = ((const float4*)src)[li];
        uint32_t h0 = cvt_bf16x2(v.y, v.x);
        uint32_t h1 = cvt_bf16x2(v.w, v.z);
        float a0 = __uint_as_float(h0 << 16), a1 = __uint_as_float(h0 & 0xFFFF0000u);
        float a2 = __uint_as_float(h1 << 16), a3 = __uint_as_float(h1 & 0xFFFF0000u);
        uint32_t l0 = cvt_bf16x2(v.y - a1, v.x - a0);
        uint32_t l1 = cvt_bf16x2(v.w - a3, v.z - a2);
        hid[li] = make_uint2(h0, h1);
        lod[li] = make_uint2(l0, l1);
    }
}

// ---------------- gemm body (HMMA, 64x64 tile, 3 hi/lo combos) ----------------
#define GR_STR 144
#define GEMM_SMEM (4 * 64 * GR_STR)
template <int MODE>
__device__ __forceinline__ void gemm_body(
    char* sm, int bx, int by,
    const __nv_bfloat16* __restrict__ Ahi, const __nv_bfloat16* __restrict__ Alo,
    const __nv_bfloat16* __restrict__ Whi, const __nv_bfloat16* __restrict__ Wlo,
    float* __restrict__ Y, __nv_bfloat16* __restrict__ Yhi, __nv_bfloat16* __restrict__ Ylo) {
    char* sAh = sm;
    char* sAl = sm + 64 * GR_STR;
    char* sWh = sm + 2 * 64 * GR_STR;
    char* sWl = sm + 3 * 64 * GR_STR;
    const uint32_t smb = smem_u32(sm);

    const int t = threadIdx.x;
    const int wid = t >> 5, lane = t & 31;
    const int row0 = bx * 64;
    const int col0 = by * 64;
    const int mw = wid >> 1, nw = wid & 1;
    const int lr = lane & 7, quad = lane >> 3;
    const uint32_t aRow = (uint32_t)(mw * 16 + (quad & 1) * 8 + lr);
    const uint32_t aKoff = (uint32_t)((quad >> 1) * 16);
    const uint32_t bRow = (uint32_t)((quad >> 1) * 8 + lr);
    const uint32_t bKoff = (uint32_t)((quad & 1) * 16);

    float c[4][4];
#pragma unroll
    for (int nf = 0; nf < 4; nf++)
#pragma unroll
        for (int k = 0; k < 4; k++) c[nf][k] = 0.f;

    for (int kc = 0; kc < 4; kc++) {
        __syncthreads();
#pragma unroll
        for (int q = 0; q < 2; q++) {
            int idx = t + q * 256;
            int r = idx >> 3, c16 = idx & 7;
            *(uint4*)(sAh + r * GR_STR + c16 * 16) =
                ((const uint4*)(Ahi + (size_t)(row0 + r) * Ee + kc * 64))[c16];
            *(uint4*)(sAl + r * GR_STR + c16 * 16) =
                ((const uint4*)(Alo + (size_t)(row0 + r) * Ee + kc * 64))[c16];
            *(uint4*)(sWh + r * GR_STR + c16 * 16) =
                ((const uint4*)(Whi + (size_t)(col0 + r) * Ee + kc * 64))[c16];
            *(uint4*)(sWl + r * GR_STR + c16 * 16) =
                ((const uint4*)(Wlo + (size_t)(col0 + r) * Ee + kc * 64))[c16];
        }
        __syncthreads();
#pragma unroll
        for (int ks = 0; ks < 4; ks++) {
            uint32_t aBase = smb + aRow * GR_STR + ks * 32 + aKoff;
            uint32_t ah0, ah1, ah2, ah3, al0, al1, al2, al3;
            ldmatrix_x4(ah0, ah1, ah2, ah3, aBase);
            ldmatrix_x4(al0, al1, al2, al3, aBase + 64 * GR_STR);
#pragma unroll
            for (int np = 0; np < 2; np++) {
                uint32_t bBase = smb + 2 * 64 * GR_STR +
                                 (nw * 32 + np * 16 + bRow) * GR_STR + ks * 32 + bKoff;
                uint32_t bh0, bh1, bh2, bh3, bl0, bl1, bl2, bl3;
                ldmatrix_x4(bh0, bh1, bh2, bh3, bBase);
                ldmatrix_x4(bl0, bl1, bl2, bl3, bBase + 64 * GR_STR);
                float* c0 = c[np * 2];
                float* c1 = c[np * 2 + 1];
                mma_bf16(c0, ah0, ah1, ah2, ah3, bh0, bh1);
                mma_bf16(c0, ah0, ah1, ah2, ah3, bl0, bl1);
                mma_bf16(c0, al0, al1, al2, al3, bh0, bh1);
                mma_bf16(c1, ah0, ah1, ah2, ah3, bh2, bh3);
                mma_bf16(c1, ah0, ah1, ah2, ah3, bl2, bl3);
                mma_bf16(c1, al0, al1, al2, al3, bh2, bh3);
            }
        }
    }

    int r0 = row0 + mw * 16 + (lane >> 2);
    int colb = col0 + nw * 32 + (lane & 3) * 2;
#pragma unroll
    for (int nf = 0; nf < 4; nf++) {
        int col = colb + nf * 8;
        if (MODE == 0) {
            *(float2*)(Y + (size_t)r0 * Ee + col) = make_float2(c[nf][0], c[nf][1]);
            *(float2*)(Y + (size_t)(r0 + 8) * Ee + col) = make_float2(c[nf][2], c[nf][3]);
        } else {
            uint32_t h0 = cvt_bf16x2(c[nf][1], c[nf][0]);
            float e0 = __uint_as_float(h0 << 16), e1 = __uint_as_float(h0 & 0xFFFF0000u);
            uint32_t l0 = cvt_bf16x2(c[nf][1] - e1, c[nf][0] - e0);
            uint32_t h1 = cvt_bf16x2(c[nf][3], c[nf][2]);
            float e2 = __uint_as_float(h1 << 16), e3 = __uint_as_float(h1 & 0xFFFF0000u);
            uint32_t l1 = cvt_bf16x2(c[nf][3] - e3, c[nf][2] - e2);
            ((uint32_t*)Yhi)[((size_t)r0 * Ee + col) >> 1] = h0;
            ((uint32_t*)Ylo)[((size_t)r0 * Ee + col) >> 1] = l0;
            ((uint32_t*)Yhi)[((size_t)(r0 + 8) * Ee + col) >> 1] = h1;
            ((uint32_t*)Ylo)[((size_t)(r0 + 8) * Ee + col) >> 1] = l1;
        }
    }
}

// ---------------- stats body ----------------
__device__ __forceinline__ void stats_body(char* sm, int i, int b,
                                           const float* __restrict__ u,
                                           const float* __restrict__ u_w,
                                           const float* __restrict__ u_b) {
    ull* s_w2 = (ull*)sm;
    ull* s_b2 = (ull*)(sm + 384);
    float* s_red = (float*)(sm + 448);
    int t = threadIdx.x;
    if (t < 48) { float w = u_w[t] * LOG2E; s_w2[t] = pack2(w, w); }
    if (t < 8)  { float bb = u_b[t] * LOG2E; s_b2[t] = pack2(bb, bb); }
    __syncthreads();

    int j0 = t * 4;
    unsigned mword = *(const unsigned*)(g_maskT + ((size_t)b * Nn + i) * Nn + j0);
    bool m0 = (mword & 0xFFu) != 0, m1 = ((mword >> 8) & 0xFFu) != 0;
    bool m2 = ((mword >> 16) & 0xFFu) != 0, m3 = ((mword >> 24) & 0xFFu) != 0;

    ulonglong2 u2[Uu];
#pragma unroll
    for (int c = 0; c < Uu; c++)
        u2[c] = *(const ulonglong2*)(u + ((size_t)(b * Uu + c) * Nn + i) * Nn + j0);

    float l[Oo];
#pragma unroll
    for (int o = 0; o < Oo; o++) {
        ull sa = s_b2[o], sb = s_b2[o];
#pragma unroll
        for (int c = 0; c < Uu; c++) {
            sa = ffma2(s_w2[o * Uu + c], u2[c].x, sa);
            sb = ffma2(s_w2[o * Uu + c], u2[c].y, sb);
        }
        float2 f0 = unpack2(sa), f1 = unpack2(sb);
        float acc = 0.f;
        if (!m0) acc += ex2f(f0.x);
        if (!m1) acc += ex2f(f0.y);
        if (!m2) acc += ex2f(f1.x);
        if (!m3) acc += ex2f(f1.y);
        l[o] = acc;
    }
#pragma unroll
    for (int o = 0; o < Oo; o++)
#pragma unroll
        for (int st = 16; st > 0; st >>= 1)
            l[o] += __shfl_xor_sync(0xFFFFFFFFu, l[o], st);
    int w = t >> 5, lane = t & 31;
    if (lane == 0) {
#pragma unroll
        for (int o = 0; o < Oo; o++) s_red[o * 9 + w] = l[o];
    }
    __syncthreads();
    if (t < 8) {
        float s = 0.f;
#pragma unroll
        for (int w2 = 0; w2 < 8; w2++) s += s_red[t * 9 + w2];
        g_l[((size_t)b * Oo + t) * Nn + i] = s;
    }
}

// ---------------- L3: gemm<1> + stats ----------------
__global__ __launch_bounds__(256) void gemm1_stats_kernel(const float* __restrict__ u,
                                                          const float* __restrict__ u_w,
                                                          const float* __restrict__ u_b) {
    __shared__ __align__(16) char sm[GEMM_SMEM];
    int bid = blockIdx.x;
    if (bid < 512) {
        gemm_body<1>(sm, bid & 127, bid >> 7,
                     g_x_hi, g_x_lo, g_vw_hi, g_vw_lo, nullptr, g_v_hi, g_v_lo);
    } else {
        int sid = bid - 512;
        stats_body(sm, sid & 1023, sid >> 10, u, u_w, u_b);
    }
}

// ---------------- L5: out projection ----------------
__global__ __launch_bounds__(256) void gemm0_kernel(float* __restrict__ Y) {
    __shared__ __align__(16) char sm[GEMM_SMEM];
    gemm_body<0>(sm, blockIdx.x, blockIdx.y,
                 g_op_hi, g_op_lo, g_ow_hi, g_ow_lo, Y, nullptr, nullptr);
}

// ---------------- L4: fused — R10 geometry, 1024 threads (32 warps) ----------------
#define SB_W2    0
#define SB_B2    384
#define SB_BETA  448
#define SB_RL    464
#define SB_BUF0  2560
#define A_HSTR   9216        // 64 rows x 144
#define A_RSTR   144         // 32 j hi (64B) | 32 j lo (64B) | 16 pad
#define V_RSTR   528
#define BA_OFF   0
#define BVH_OFF  36864       // A = 4*9216
#define BVL_OFF  53760       // +32*528
#define BUF_STR  70656       // +32*528
#define SB_TOT   (2560 + 2 * 70656)   // 143872

__global__ __launch_bounds__(1024, 1) void fused_kernel(const float* __restrict__ u,
                                                        const float* __restrict__ u_w,
                                                        const float* __restrict__ u_b,
                                                        float* __restrict__ attn_out) {
    extern __shared__ char smc[];
    const uint32_t smem_base = smem_u32(smc);
    ull*   s_w2   = (ull*)(smc + SB_W2);
    ull*   s_b2   = (ull*)(smc + SB_B2);
    float* s_beta = (float*)(smc + SB_BETA);
    float* s_rl   = (float*)(smc + SB_RL);

    const int t = threadIdx.x;
    const int wid = t >> 5;
    const int lane = t & 31;
    const int b = blockIdx.y;
    const int i0 = blockIdx.x * 64;

    if (t < 48)      { float w = u_w[t] * LOG2E; s_w2[t] = pack2(w, w); }
    else if (t < 56) { float bb = u_b[t - 48] * LOG2E; s_b2[t - 48] = pack2(bb, bb); }
    else if (t == 56) *s_beta = g_beta;
    if (t < 512) {
        int o = t >> 6, il2 = t & 63;
        s_rl[t] = 1.0f / g_l[((size_t)b * Oo + o) * Nn + i0 + il2];
    }
    __syncthreads();

    const float beta = *s_beta;
    // phase A mapping: 1 row x 2 j per thread (64 rows x 16 jq)
    const int jq = t & 15;
    const int il = t >> 4;
    const int gi = i0 + il;
    // phase B mapping: warp -> (head, 16-row group, 32-col half)
    const int h_b = wid >> 3;
    const int rg = (wid >> 1) & 3;
    const int nh = wid & 1;
    const int lg = lane >> 3, lr = lane & 7;
    const uint32_t a_lm_row = (uint32_t)(rg * 16 + (lg & 1) * 8 + lr);
    const uint32_t a_lm_kh = (uint32_t)(lg >> 1);
    const uint32_t b_lm_krow = (uint32_t)((lg & 1) * 8 + lr);
    const uint32_t b_lm_ncol = (uint32_t)(h_b * 64 + nh * 32 + (lg >> 1) * 8);

    float rl[Oo];
#pragma unroll
    for (int o = 0; o < Oo; o++) rl[o] = s_rl[o * 64 + il];

    float c[4][4];
#pragma unroll
    for (int nf = 0; nf < 4; nf++)
#pragma unroll
        for (int k = 0; k < 4; k++) c[nf][k] = 0.f;

    // V tile cp.async: 2048 chunks of 16B / 1024 thr = 2 each
    auto cp_v = [&](int jt, uint32_t buf_sm) {
#pragma unroll
        for (int q = 0; q < 2; q++) {
            int cidx = t + q * 1024;
            int isLo = cidx >> 10;
            int r = (cidx >> 5) & 31;
            int k16 = cidx & 31;
            const __nv_bfloat16* src = (isLo ? g_v_lo : g_v_hi) +
                ((size_t)b * Nn + jt * 32 + r) * Ee + k16 * 8;
            cp_async16(buf_sm + (isLo ? BVL_OFF : BVH_OFF) + r * V_RSTR + k16 * 16, src);
        }
        cp_async_commit();
    };

    auto load_u = [&](int jg0, ull* u1, unsigned& mw) {
        mw = *(const unsigned short*)(g_maskT + ((size_t)b * Nn + gi) * Nn + jg0);
#pragma unroll
        for (int cc = 0; cc < Uu; cc++) {
            uint2 raw = __ldcs((const uint2*)(u + ((size_t)(b * Uu + cc) * Nn + gi) * Nn + jg0));
            u1[cc] = pack2u(raw.x, raw.y);
        }
    };

    auto phaseA = [&](int jt, char* buf, const ull* u1, unsigned mword) {
        const int jg0 = jt * 32 + jq * 2;
        bool m0 = (mword & 0xFFu) != 0, m1 = ((mword >> 8) & 0xFFu) != 0;
        const uint32_t abyte = (uint32_t)(il * A_RSTR + jq * 4);
#pragma unroll
        for (int h = 0; h < Hh; h++) {
            int o0 = 2 * h, o1 = 2 * h + 1;
            ull sa0 = s_b2[o0], sa1 = s_b2[o1];
#pragma unroll
            for (int cc = 0; cc < Uu; cc++) {
                sa0 = ffma2(s_w2[o0 * Uu + cc], u1[cc], sa0);
                sa1 = ffma2(s_w2[o1 * Uu + cc], u1[cc], sa1);
            }
            float2 f0 = unpack2(sa0), f1 = unpack2(sa1);
            float p00 = m0 ? 0.f : ex2f(f0.x) * rl[o0];
            float p01 = m1 ? 0.f : ex2f(f0.y) * rl[o0];
            float p10 = m0 ? 0.f : ex2f(f1.x) * rl[o1];
            float p11 = m1 ? 0.f : ex2f(f1.y) * rl[o1];
            float a0 = p00 - beta * p10;
            float a1 = p01 - beta * p11;
            __stcs((float2*)(attn_out + ((size_t)(b * Hh + h) * Nn + gi) * Nn + jg0),
                   make_float2(a0, a1));
            uint32_t hA = cvt_bf16x2(a1, a0);
            float e0 = __uint_as_float(hA << 16);
            float e1 = __uint_as_float(hA & 0xFFFF0000u);
            uint32_t lA = cvt_bf16x2(a1 - e1, a0 - e0);
            char* ap = buf + BA_OFF + h * A_HSTR + abyte;
            *(uint32_t*)(ap)      = hA;
            *(uint32_t*)(ap + 64) = lA;
        }
    };

    // ---- prologue: tile 0 ----
    {
        char* buf0 = smc + SB_BUF0;
        cp_v(0, smem_base + SB_BUF0);
        ull u1[Uu];
        unsigned mw;
        load_u(jq * 2, u1, mw);
        phaseA(0, buf0, u1, mw);
        cp_async_wait0();
        __syncthreads();
    }

    // ---- pipelined main loop (32 tiles of 32 j) ----
    for (int jt = 0; jt < 32; jt++) {
        char* bufN = smc + SB_BUF0 + ((jt + 1) & 1) * BUF_STR;
        const uint32_t bufN_sm = smem_base + SB_BUF0 + ((jt + 1) & 1) * BUF_STR;
        const uint32_t bufC_sm = smem_base + SB_BUF0 + (jt & 1) * BUF_STR;
        const bool has_next = (jt < 31);

        ull u1[Uu];
        unsigned mw = 0;
        if (has_next) {
            cp_v(jt + 1, bufN_sm);
            load_u((jt + 1) * 32 + jq * 2, u1, mw);
        }

        // phase B: MMA from current buffer (16 rows x 32 cols per warp)
#pragma unroll
        for (int ks = 0; ks < 2; ks++) {
            uint32_t aAddr = bufC_sm + BA_OFF + h_b * A_HSTR + a_lm_row * A_RSTR +
                             ks * 32 + a_lm_kh * 16;
            uint32_t ah0, ah1, ah2, ah3, al0, al1, al2, al3;
            ldmatrix_x4(ah0, ah1, ah2, ah3, aAddr);
            ldmatrix_x4(al0, al1, al2, al3, aAddr + 64);
#pragma unroll
            for (int np = 0; np < 2; np++) {
                uint32_t bAddr = bufC_sm + BVH_OFF +
                                 (ks * 16 + b_lm_krow) * V_RSTR +
                                 (b_lm_ncol + np * 16) * 2;
                uint32_t bh0, bh1, bh2, bh3, bl0, bl1, bl2, bl3;
                ldmatrix_x4_trans(bh0, bh1, bh2, bh3, bAddr);
                ldmatrix_x4_trans(bl0, bl1, bl2, bl3, bAddr + (BVL_OFF - BVH_OFF));
                float* c0 = c[np * 2];
                float* c1 = c[np * 2 + 1];
                mma_bf16(c0, ah0, ah1, ah2, ah3, bh0, bh1);
                mma_bf16(c0, ah0, ah1, ah2, ah3, bl0, bl1);
                mma_bf16(c0, al0, al1, al2, al3, bh0, bh1);
                mma_bf16(c1, ah0, ah1, ah2, ah3, bh2, bh3);
                mma_bf16(c1, ah0, ah1, ah2, ah3, bl2, bl3);
                mma_bf16(c1, al0, al1, al2, al3, bh2, bh3);
            }
        }

        if (has_next) {
            phaseA(jt + 1, bufN, u1, mw);
            cp_async_wait0();
        }
        __syncthreads();
    }

    // ---- epilogue: each warp writes 16 rows x 32 cols ----
    {
        int r = lane >> 2, cq = lane & 3;
        int go0 = i0 + rg * 16 + r;
        int go1 = go0 + 8;
#pragma unroll
        for (int nf = 0; nf < 4; nf++) {
            int col = h_b * 64 + nh * 32 + nf * 8 + cq * 2;
            uint32_t h0 = cvt_bf16x2(c[nf][1], c[nf][0]);
            float e0 = __uint_as_float(h0 << 16), e1 = __uint_as_float(h0 & 0xFFFF0000u);
            uint32_t l0 = cvt_bf16x2(c[nf][1] - e1, c[nf][0] - e0);
            uint32_t h1 = cvt_bf16x2(c[nf][3], c[nf][2]);
            float e2 = __uint_as_float(h1 << 16), e3 = __uint_as_float(h1 & 0xFFFF0000u);
            uint32_t l1 = cvt_bf16x2(c[nf][3] - e3, c[nf][2] - e2);
            ((uint32_t*)g_op_hi)[(((size_t)b * Nn + go0) * Ee + col) >> 1] = h0;
            ((uint32_t*)g_op_lo)[(((size_t)b * Nn + go0) * Ee + col) >> 1] = l0;
            ((uint32_t*)g_op_hi)[(((size_t)b * Nn + go1) * Ee + col) >> 1] = h1;
            ((uint32_t*)g_op_lo)[(((size_t)b * Nn + go1) * Ee + col) >> 1] = l1;
        }
    }
}

// ---------------- launch ----------------
extern "C" void kernel_launch(void* const* d_in, const int* in_sizes, int n_in,
                              void* d_out, int out_size) {
    const float* x     = (const float*)d_in[0];
    const float* u     = (const float*)d_in[1];
    const void*  umask = d_in[2];
    const float* v_w   = (const float*)d_in[3];
    const float* out_w = (const float*)d_in[4];
    const float* u_w   = (const float*)d_in[5];
    const float* u_b   = (const float*)d_in[6];
    const float* lq    = (const float*)d_in[7];
    const float* lk    = (const float*)d_in[8];

    float* out = (float*)d_out;
    const size_t OUT_ELEMS  = (size_t)Bb * Nn * Ee;
    const size_t ATTN_ELEMS = (size_t)Bb * Hh * Nn * Nn;
    float* attn_out  = out + OUT_ELEMS;
    float* beta_slot = out + OUT_ELEMS + ATTN_ELEMS;

    static bool attr_set = false;
    if (!attr_set) {
        cudaFuncSetAttribute(fused_kernel, cudaFuncAttributeMaxDynamicSharedMemorySize, SB_TOT);
        attr_set = true;
    }

    detect_beta_kernel<<<1, 256>>>((const unsigned char*)umask, lq, lk, beta_slot);  // #1
    prep_kernel<<<PREP_GRID, 256>>>(umask, x, v_w, out_w);                            // #2
    gemm1_stats_kernel<<<512 + Nn * Bb, 256>>>(u, u_w, u_b);                          // #3
    fused_kernel<<<dim3(16, 8), 1024, SB_TOT>>>(u, u_w, u_b, attn_out);               // #4 (profiled)
    gemm0_kernel<<<dim3(128, 4), 256>>>(out);                                         // #5
    (void)in_sizes; (void)n_in; (void)out_size;
}

// round 14
// speedup vs baseline: 1.1371x; 1.0348x over previous
#include <cuda_runtime.h>
#include <cuda_bf16.h>
#include <math.h>
#include <stdint.h>

#define Bb 8
#define Nn 1024
#define Ee 256
#define Hh 4
#define Uu 6
#define Oo 8
#define LAMBDA_INIT 0.63212055882855767840f
#define LOG2E 1.44269504088896340736f

typedef unsigned long long ull;

// ---------------- scratch (static device memory; no allocation) ----------------
__device__ unsigned char g_maskT[(size_t)Bb * Nn * Nn];
__device__ __nv_bfloat16 g_v_hi[(size_t)Bb * Nn * Ee];
__device__ __nv_bfloat16 g_v_lo[(size_t)Bb * Nn * Ee];
__device__ __nv_bfloat16 g_x_hi[(size_t)Bb * Nn * Ee];
__device__ __nv_bfloat16 g_x_lo[(size_t)Bb * Nn * Ee];
__device__ __nv_bfloat16 g_op_hi[(size_t)Bb * Nn * Ee];
__device__ __nv_bfloat16 g_op_lo[(size_t)Bb * Nn * Ee];
__device__ __nv_bfloat16 g_vw_hi[(size_t)Ee * Ee];
__device__ __nv_bfloat16 g_vw_lo[(size_t)Ee * Ee];
__device__ __nv_bfloat16 g_ow_hi[(size_t)Ee * Ee];
__device__ __nv_bfloat16 g_ow_lo[(size_t)Ee * Ee];
__device__ float g_l[(size_t)Bb * Oo * Nn];
__device__ float g_beta;
__device__ int   g_mask_kind;

// ---------------- helpers ----------------
__device__ __forceinline__ ull pack2(float a, float b) {
    ull r; asm("mov.b64 %0, {%1,%2};" : "=l"(r) : "f"(a), "f"(b)); return r;
}
__device__ __forceinline__ float2 unpack2(ull v) {
    float2 r; asm("mov.b64 {%0,%1}, %2;" : "=f"(r.x), "=f"(r.y) : "l"(v)); return r;
}
__device__ __forceinline__ ull ffma2(ull a, ull b, ull c) {
    ull d; asm("fma.rn.f32x2 %0, %1, %2, %3;" : "=l"(d) : "l"(a), "l"(b), "l"(c)); return d;
}
__device__ __forceinline__ uint32_t cvt_bf16x2(float a1, float a0) {
    uint32_t r; asm("cvt.rn.bf16x2.f32 %0, %1, %2;" : "=r"(r) : "f"(a1), "f"(a0)); return r;
}
__device__ __forceinline__ float ex2f(float x) {
    float r; asm("ex2.approx.f32 %0, %1;" : "=f"(r) : "f"(x)); return r;
}
__device__ __forceinline__ uint32_t smem_u32(const void* p) {
    uint32_t a;
    asm("{ .reg .u64 t; cvta.to.shared.u64 t, %1; cvt.u32.u64 %0, t; }" : "=r"(a) : "l"(p));
    return a;
}
__device__ __forceinline__ void cp_async16(uint32_t smem_addr, const void* gmem) {
    asm volatile("cp.async.cg.shared.global [%0], [%1], 16;" :: "r"(smem_addr), "l"(gmem));
}
__device__ __forceinline__ void cp_async_commit() {
    asm volatile("cp.async.commit_group;" ::: "memory");
}
__device__ __forceinline__ void cp_async_wait0() {
    asm volatile("cp.async.wait_group 0;" ::: "memory");
}
__device__ __forceinline__ void cp_async_wait1() {
    asm volatile("cp.async.wait_group 1;" ::: "memory");
}
__device__ __forceinline__ void ldmatrix_x4(uint32_t& r0, uint32_t& r1, uint32_t& r2,
                                            uint32_t& r3, uint32_t addr) {
    asm volatile("ldmatrix.sync.aligned.m8n8.x4.shared.b16 {%0,%1,%2,%3}, [%4];"
                 : "=r"(r0), "=r"(r1), "=r"(r2), "=r"(r3) : "r"(addr));
}
__device__ __forceinline__ void ldmatrix_x4_trans(uint32_t& r0, uint32_t& r1, uint32_t& r2,
                                                  uint32_t& r3, uint32_t addr) {
    asm volatile("ldmatrix.sync.aligned.m8n8.x4.trans.shared.b16 {%0,%1,%2,%3}, [%4];"
                 : "=r"(r0), "=r"(r1), "=r"(r2), "=r"(r3) : "r"(addr));
}
__device__ __forceinline__ void mma_bf16(float* c, uint32_t a0, uint32_t a1, uint32_t a2,
                                         uint32_t a3, uint32_t b0, uint32_t b1) {
    asm volatile(
        "mma.sync.aligned.m16n8k16.row.col.f32.bf16.bf16.f32 "
        "{%0,%1,%2,%3}, {%4,%5,%6,%7}, {%8,%9}, {%0,%1,%2,%3};"
        : "+f"(c[0]), "+f"(c[1]), "+f"(c[2]), "+f"(c[3])
        : "r"(a0), "r"(a1), "r"(a2), "r"(a3), "r"(b0), "r"(b1));
}

// ---------------- L1: detect mask dtype + beta ----------------
__global__ void detect_beta_kernel(const unsigned char* __restrict__ raw,
                                   const float* __restrict__ lq,
                                   const float* __restrict__ lk,
                                   float* __restrict__ beta_slot) {
    __shared__ int cnt[4];
    __shared__ float red[128];
    int t = threadIdx.x;
    if (t < 4) cnt[t] = 0;
    if (t < 128) red[t] = (t < 100) ? lq[t] * lk[t] : 0.f;
    __syncthreads();
    for (int i = t; i < 16384; i += blockDim.x)
        if (raw[i]) atomicAdd(&cnt[i & 3], 1);
    for (int st = 64; st > 0; st >>= 1) {
        if (t < st) red[t] += red[t + st];
        __syncthreads();
    }
    if (t == 0) {
        int kind;
        if (cnt[1] == 0 && cnt[2] == 0 && cnt[3] == 0) kind = 1;
        else if (cnt[0] == 0 && cnt[1] == 0)           kind = 2;
        else                                            kind = 0;
        g_mask_kind = kind;
        float lam1 = expf(red[0]);
        float beta = 1.f / (1.f + expf(-lam1 * LAMBDA_INIT));
        g_beta = beta;
        *beta_slot = beta;
    }
}

// ---------------- L2: prep = mask transpose + splits ----------------
#define NX4 ((int)((size_t)Bb * Nn * Ee / 4))
#define NW4 (Ee * Ee / 4)
#define PREP_GRID (8192 + (NX4 + 2 * NW4) / 256)

__global__ __launch_bounds__(256) void prep_kernel(const void* __restrict__ rawv,
                                                   const float* __restrict__ x,
                                                   const float* __restrict__ vw,
                                                   const float* __restrict__ ow) {
    int bid = blockIdx.x;
    if (bid < 8192) {
        __shared__ unsigned char tile[32][33];
        int xt = bid & 31, yt = (bid >> 5) & 31, b = bid >> 10;
        int i0 = xt * 32, j0 = yt * 32;
        int tx = threadIdx.x & 31, ty0 = threadIdx.x >> 5;
        int kind = g_mask_kind;
#pragma unroll
        for (int k = 0; k < 4; k++) {
            int ty = ty0 + k * 8;
            size_t src = ((size_t)b * Nn + (j0 + ty)) * Nn + (i0 + tx);
            unsigned char v;
            if (kind == 0)      v = (((const unsigned char*)rawv)[src] != 0);
            else if (kind == 1) v = (((const int*)rawv)[src] != 0);
            else                v = (((const float*)rawv)[src] != 0.f);
            tile[ty][tx] = v;
        }
        __syncthreads();
#pragma unroll
        for (int k = 0; k < 4; k++) {
            int ty = ty0 + k * 8;
            g_maskT[((size_t)b * Nn + (i0 + ty)) * Nn + (j0 + tx)] = tile[tx][ty];
        }
    } else {
        int idx = (bid - 8192) * 256 + threadIdx.x;
        const float* src;
        uint2 *hid, *lod;
        int li;
        if (idx < NX4) {
            src = x; hid = (uint2*)g_x_hi; lod = (uint2*)g_x_lo; li = idx;
        } else if (idx < NX4 + NW4) {
            src = vw; hid = (uint2*)g_vw_hi; lod = (uint2*)g_vw_lo; li = idx - NX4;
        } else {
            src = ow; hid = (uint2*)g_ow_hi; lod = (uint2*)g_ow_lo; li = idx - NX4 - NW4;
        }
        float4 v = ((const float4*)src)[li];
        uint32_t h0 = cvt_bf16x2(v.y, v.x);
        uint32_t h1 = cvt_bf16x2(v.w, v.z);
        float a0 = __uint_as_float(h0 << 16), a1 = __uint_as_float(h0 & 0xFFFF0000u);
        float a2 = __uint_as_float(h1 << 16), a3 = __uint_as_float(h1 & 0xFFFF0000u);
        uint32_t l0 = cvt_bf16x2(v.y - a1, v.x - a0);
        uint32_t l1 = cvt_bf16x2(v.w - a3, v.z - a2);
        hid[li] = make_uint2(h0, h1);
        lod[li] = make_uint2(l0, l1);
    }
}

// ---------------- gemm body (HMMA, 64x64 tile, 3 hi/lo combos) ----------------
#define GR_STR 144
#define GEMM_SMEM (4 * 64 * GR_STR)
template <int MODE>
__device__ __forceinline__ void gemm_body(
    char* sm, int bx, int by,
    const __nv_bfloat16* __restrict__ Ahi, const __nv_bfloat16* __restrict__ Alo,
    const __nv_bfloat16* __restrict__ Whi, const __nv_bfloat16* __restrict__ Wlo,
    float* __restrict__ Y, __nv_bfloat16* __restrict__ Yhi, __nv_bfloat16* __restrict__ Ylo) {
    char* sAh = sm;
    char* sAl = sm + 64 * GR_STR;
    char* sWh = sm + 2 * 64 * GR_STR;
    char* sWl = sm + 3 * 64 * GR_STR;
    const uint32_t smb = smem_u32(sm);

    const int t = threadIdx.x;
    const int wid = t >> 5, lane = t & 31;
    const int row0 = bx * 64;
    const int col0 = by * 64;
    const int mw = wid >> 1, nw = wid & 1;
    const int lr = lane & 7, quad = lane >> 3;
    const uint32_t aRow = (uint32_t)(mw * 16 + (quad & 1) * 8 + lr);
    const uint32_t aKoff = (uint32_t)((quad >> 1) * 16);
    const uint32_t bRow = (uint32_t)((quad >> 1) * 8 + lr);
    const uint32_t bKoff = (uint32_t)((quad & 1) * 16);

    float c[4][4];
#pragma unroll
    for (int nf = 0; nf < 4; nf++)
#pragma unroll
        for (int k = 0; k < 4; k++) c[nf][k] = 0.f;

    for (int kc = 0; kc < 4; kc++) {
        __syncthreads();
#pragma unroll
        for (int q = 0; q < 2; q++) {
            int idx = t + q * 256;
            int r = idx >> 3, c16 = idx & 7;
            *(uint4*)(sAh + r * GR_STR + c16 * 16) =
                ((const uint4*)(Ahi + (size_t)(row0 + r) * Ee + kc * 64))[c16];
            *(uint4*)(sAl + r * GR_STR + c16 * 16) =
                ((const uint4*)(Alo + (size_t)(row0 + r) * Ee + kc * 64))[c16];
            *(uint4*)(sWh + r * GR_STR + c16 * 16) =
                ((const uint4*)(Whi + (size_t)(col0 + r) * Ee + kc * 64))[c16];
            *(uint4*)(sWl + r * GR_STR + c16 * 16) =
                ((const uint4*)(Wlo + (size_t)(col0 + r) * Ee + kc * 64))[c16];
        }
        __syncthreads();
#pragma unroll
        for (int ks = 0; ks < 4; ks++) {
            uint32_t aBase = smb + aRow * GR_STR + ks * 32 + aKoff;
            uint32_t ah0, ah1, ah2, ah3, al0, al1, al2, al3;
            ldmatrix_x4(ah0, ah1, ah2, ah3, aBase);
            ldmatrix_x4(al0, al1, al2, al3, aBase + 64 * GR_STR);
#pragma unroll
            for (int np = 0; np < 2; np++) {
                uint32_t bBase = smb + 2 * 64 * GR_STR +
                                 (nw * 32 + np * 16 + bRow) * GR_STR + ks * 32 + bKoff;
                uint32_t bh0, bh1, bh2, bh3, bl0, bl1, bl2, bl3;
                ldmatrix_x4(bh0, bh1, bh2, bh3, bBase);
                ldmatrix_x4(bl0, bl1, bl2, bl3, bBase + 64 * GR_STR);
                float* c0 = c[np * 2];
                float* c1 = c[np * 2 + 1];
                mma_bf16(c0, ah0, ah1, ah2, ah3, bh0, bh1);
                mma_bf16(c0, ah0, ah1, ah2, ah3, bl0, bl1);
                mma_bf16(c0, al0, al1, al2, al3, bh0, bh1);
                mma_bf16(c1, ah0, ah1, ah2, ah3, bh2, bh3);
                mma_bf16(c1, ah0, ah1, ah2, ah3, bl2, bl3);
                mma_bf16(c1, al0, al1, al2, al3, bh2, bh3);
            }
        }
    }

    int r0 = row0 + mw * 16 + (lane >> 2);
    int colb = col0 + nw * 32 + (lane & 3) * 2;
#pragma unroll
    for (int nf = 0; nf < 4; nf++) {
        int col = colb + nf * 8;
        if (MODE == 0) {
            *(float2*)(Y + (size_t)r0 * Ee + col) = make_float2(c[nf][0], c[nf][1]);
            *(float2*)(Y + (size_t)(r0 + 8) * Ee + col) = make_float2(c[nf][2], c[nf][3]);
        } else {
            uint32_t h0 = cvt_bf16x2(c[nf][1], c[nf][0]);
            float e0 = __uint_as_float(h0 << 16), e1 = __uint_as_float(h0 & 0xFFFF0000u);
            uint32_t l0 = cvt_bf16x2(c[nf][1] - e1, c[nf][0] - e0);
            uint32_t h1 = cvt_bf16x2(c[nf][3], c[nf][2]);
            float e2 = __uint_as_float(h1 << 16), e3 = __uint_as_float(h1 & 0xFFFF0000u);
            uint32_t l1 = cvt_bf16x2(c[nf][3] - e3, c[nf][2] - e2);
            ((uint32_t*)Yhi)[((size_t)r0 * Ee + col) >> 1] = h0;
            ((uint32_t*)Ylo)[((size_t)r0 * Ee + col) >> 1] = l0;
            ((uint32_t*)Yhi)[((size_t)(r0 + 8) * Ee + col) >> 1] = h1;
            ((uint32_t*)Ylo)[((size_t)(r0 + 8) * Ee + col) >> 1] = l1;
        }
    }
}

// ---------------- stats body ----------------
__device__ __forceinline__ void stats_body(char* sm, int i, int b,
                                           const float* __restrict__ u,
                                           const float* __restrict__ u_w,
                                           const float* __restrict__ u_b) {
    ull* s_w2 = (ull*)sm;
    ull* s_b2 = (ull*)(sm + 384);
    float* s_red = (float*)(sm + 448);
    int t = threadIdx.x;
    if (t < 48) { float w = u_w[t] * LOG2E; s_w2[t] = pack2(w, w); }
    if (t < 8)  { float bb = u_b[t] * LOG2E; s_b2[t] = pack2(bb, bb); }
    __syncthreads();

    int j0 = t * 4;
    unsigned mword = *(const unsigned*)(g_maskT + ((size_t)b * Nn + i) * Nn + j0);
    bool m0 = (mword & 0xFFu) != 0, m1 = ((mword >> 8) & 0xFFu) != 0;
    bool m2 = ((mword >> 16) & 0xFFu) != 0, m3 = ((mword >> 24) & 0xFFu) != 0;

    ulonglong2 u2[Uu];
#pragma unroll
    for (int c = 0; c < Uu; c++)
        u2[c] = __ldcs((const ulonglong2*)(u + ((size_t)(b * Uu + c) * Nn + i) * Nn + j0));

    float l[Oo];
#pragma unroll
    for (int o = 0; o < Oo; o++) {
        ull sa = s_b2[o], sb = s_b2[o];
#pragma unroll
        for (int c = 0; c < Uu; c++) {
            sa = ffma2(s_w2[o * Uu + c], u2[c].x, sa);
            sb = ffma2(s_w2[o * Uu + c], u2[c].y, sb);
        }
        float2 f0 = unpack2(sa), f1 = unpack2(sb);
        float acc = 0.f;
        if (!m0) acc += ex2f(f0.x);
        if (!m1) acc += ex2f(f0.y);
        if (!m2) acc += ex2f(f1.x);
        if (!m3) acc += ex2f(f1.y);
        l[o] = acc;
    }
#pragma unroll
    for (int o = 0; o < Oo; o++)
#pragma unroll
        for (int st = 16; st > 0; st >>= 1)
            l[o] += __shfl_xor_sync(0xFFFFFFFFu, l[o], st);
    int w = t >> 5, lane = t & 31;
    if (lane == 0) {
#pragma unroll
        for (int o = 0; o < Oo; o++) s_red[o * 9 + w] = l[o];
    }
    __syncthreads();
    if (t < 8) {
        float s = 0.f;
#pragma unroll
        for (int w2 = 0; w2 < 8; w2++) s += s_red[t * 9 + w2];
        g_l[((size_t)b * Oo + t) * Nn + i] = s;
    }
}

// ---------------- L3: gemm<1> + stats ----------------
__global__ __launch_bounds__(256) void gemm1_stats_kernel(const float* __restrict__ u,
                                                          const float* __restrict__ u_w,
                                                          const float* __restrict__ u_b) {
    __shared__ __align__(16) char sm[GEMM_SMEM];
    int bid = blockIdx.x;
    if (bid < 512) {
        gemm_body<1>(sm, bid & 127, bid >> 7,
                     g_x_hi, g_x_lo, g_vw_hi, g_vw_lo, nullptr, g_v_hi, g_v_lo);
    } else {
        int sid = bid - 512;
        stats_body(sm, sid & 1023, sid >> 10, u, u_w, u_b);
    }
}

// ---------------- L5: out projection ----------------
__global__ __launch_bounds__(256) void gemm0_kernel(float* __restrict__ Y) {
    __shared__ __align__(16) char sm[GEMM_SMEM];
    gemm_body<0>(sm, blockIdx.x, blockIdx.y,
                 g_op_hi, g_op_lo, g_ow_hi, g_ow_lo, Y, nullptr, nullptr);
}

// ---------------- L4: fused — R10 geometry + split-group cp.async for u ----------------
#define SB_W2    0
#define SB_B2    384
#define SB_BETA  448
#define SB_RL    464
#define SB_BUF0  2560
#define A_HSTR   9216        // 64 rows x 144
#define A_RSTR   144         // 32 j hi (64B) | 32 j lo (64B) | 16 pad
#define V_RSTR   528
#define BA_OFF   0
#define BVH_OFF  36864       // A = 4*9216
#define BVL_OFF  53760       // +32*528
#define BUF_STR  70656       // +32*528
#define SB_U     (2560 + 2 * 70656)   // 143872; u tile: 6ch x 64row x 128B = 48KB
#define U_CHS    8192
#define U_RSTR   128
#define SB_TOT   (143872 + 49152)     // 193024

__global__ __launch_bounds__(512, 1) void fused_kernel(const float* __restrict__ u,
                                                       const float* __restrict__ u_w,
                                                       const float* __restrict__ u_b,
                                                       float* __restrict__ attn_out) {
    extern __shared__ char smc[];
    const uint32_t smem_base = smem_u32(smc);
    ull*   s_w2   = (ull*)(smc + SB_W2);
    ull*   s_b2   = (ull*)(smc + SB_B2);
    float* s_beta = (float*)(smc + SB_BETA);
    float* s_rl   = (float*)(smc + SB_RL);

    const int t = threadIdx.x;
    const int wid = t >> 5;
    const int lane = t & 31;
    const int b = blockIdx.y;
    const int i0 = blockIdx.x * 64;

    if (t < 48)      { float w = u_w[t] * LOG2E; s_w2[t] = pack2(w, w); }
    else if (t < 56) { float bb = u_b[t - 48] * LOG2E; s_b2[t - 48] = pack2(bb, bb); }
    else if (t == 56) *s_beta = g_beta;
    {
        int o = t >> 6, il2 = t & 63;
        s_rl[t] = 1.0f / g_l[((size_t)b * Oo + o) * Nn + i0 + il2];
    }
    __syncthreads();

    const float beta = *s_beta;
    // phase A mapping: 1 row x 4 j per thread (64 rows x 8 jq)
    const int jq = t & 7;
    const int il = t >> 3;
    const int gi = i0 + il;
    // phase B mapping: warp -> (head, 16-row group)
    const int h_b = wid >> 2;
    const int ig = wid & 3;
    const int lg = lane >> 3, lr = lane & 7;
    const uint32_t a_lm_row = (uint32_t)(ig * 16 + (lg & 1) * 8 + lr);
    const uint32_t a_lm_kh = (uint32_t)(lg >> 1);
    const uint32_t b_lm_krow = (uint32_t)((lg & 1) * 8 + lr);
    const uint32_t b_lm_ncol = (uint32_t)(h_b * 64 + (lg >> 1) * 8);

    float rl[Oo];
#pragma unroll
    for (int o = 0; o < Oo; o++) rl[o] = s_rl[o * 64 + il];

    float c[8][4];
#pragma unroll
    for (int nf = 0; nf < 8; nf++)
#pragma unroll
        for (int k = 0; k < 4; k++) c[nf][k] = 0.f;

    // u tile via cp.async: own group (committed FIRST each tile)
    const uint32_t u_dst = smem_base + SB_U + il * U_RSTR + jq * 16;
    auto cp_u = [&](int jt) {
#pragma unroll
        for (int cc = 0; cc < Uu; cc++) {
            const float* src = u + ((size_t)(b * Uu + cc) * Nn + gi) * Nn + jt * 32 + jq * 4;
            cp_async16(u_dst + cc * U_CHS, src);
        }
        cp_async_commit();
    };
    // V tile via cp.async: second group
    auto cp_v = [&](int jt, uint32_t buf_sm) {
#pragma unroll
        for (int q = 0; q < 4; q++) {
            int cidx = t + q * 512;
            int isLo = cidx >> 10;
            int r = (cidx >> 5) & 31;
            int k16 = cidx & 31;
            const __nv_bfloat16* src = (isLo ? g_v_lo : g_v_hi) +
                ((size_t)b * Nn + jt * 32 + r) * Ee + k16 * 8;
            cp_async16(buf_sm + (isLo ? BVL_OFF : BVH_OFF) + r * V_RSTR + k16 * 16, src);
        }
        cp_async_commit();
    };

    auto phaseA = [&](int jt, char* buf, unsigned mword) {
        const int jg0 = jt * 32 + jq * 4;
        // u from smem (conflict-free: addresses sequential within warp)
        ulonglong2 u2[Uu];
#pragma unroll
        for (int cc = 0; cc < Uu; cc++)
            u2[cc] = *(const ulonglong2*)(smc + SB_U + cc * U_CHS + il * U_RSTR + jq * 16);
        bool m0 = (mword & 0xFFu) != 0, m1 = ((mword >> 8) & 0xFFu) != 0;
        bool m2 = ((mword >> 16) & 0xFFu) != 0, m3 = ((mword >> 24) & 0xFFu) != 0;
        const uint32_t abyte = (uint32_t)(il * A_RSTR + jq * 8);
#pragma unroll
        for (int h = 0; h < Hh; h++) {
            int o0 = 2 * h, o1 = 2 * h + 1;
            ull sa0 = s_b2[o0], sb0 = s_b2[o0];
            ull sa1 = s_b2[o1], sb1 = s_b2[o1];
#pragma unroll
            for (int cc = 0; cc < Uu; cc++) {
                sa0 = ffma2(s_w2[o0 * Uu + cc], u2[cc].x, sa0);
                sb0 = ffma2(s_w2[o0 * Uu + cc], u2[cc].y, sb0);
                sa1 = ffma2(s_w2[o1 * Uu + cc], u2[cc].x, sa1);
                sb1 = ffma2(s_w2[o1 * Uu + cc], u2[cc].y, sb1);
            }
            float2 f00 = unpack2(sa0), f01 = unpack2(sb0);
            float2 f10 = unpack2(sa1), f11 = unpack2(sb1);
            float p00 = m0 ? 0.f : ex2f(f00.x) * rl[o0];
            float p01 = m1 ? 0.f : ex2f(f00.y) * rl[o0];
            float p02 = m2 ? 0.f : ex2f(f01.x) * rl[o0];
            float p03 = m3 ? 0.f : ex2f(f01.y) * rl[o0];
            float p10 = m0 ? 0.f : ex2f(f10.x) * rl[o1];
            float p11 = m1 ? 0.f : ex2f(f10.y) * rl[o1];
            float p12 = m2 ? 0.f : ex2f(f11.x) * rl[o1];
            float p13 = m3 ? 0.f : ex2f(f11.y) * rl[o1];
            float a0 = p00 - beta * p10;
            float a1 = p01 - beta * p11;
            float a2 = p02 - beta * p12;
            float a3 = p03 - beta * p13;
            __stcs((float4*)(attn_out + ((size_t)(b * Hh + h) * Nn + gi) * Nn + jg0),
                   make_float4(a0, a1, a2, a3));
            uint32_t hA = cvt_bf16x2(a1, a0);
            uint32_t hB = cvt_bf16x2(a3, a2);
            float e0 = __uint_as_float(hA << 16);
            float e1 = __uint_as_float(hA & 0xFFFF0000u);
            float e2 = __uint_as_float(hB << 16);
            float e3 = __uint_as_float(hB & 0xFFFF0000u);
            uint32_t lA = cvt_bf16x2(a1 - e1, a0 - e0);
            uint32_t lB = cvt_bf16x2(a3 - e3, a2 - e2);
            char* ap = buf + BA_OFF + h * A_HSTR + abyte;
            *(uint2*)(ap)      = make_uint2(hA, hB);
            *(uint2*)(ap + 64) = make_uint2(lA, lB);
        }
    };

    // ---- prologue: tile 0 ----
    {
        char* buf0 = smc + SB_BUF0;
        cp_u(0);
        cp_v(0, smem_base + SB_BUF0);
        unsigned mw = __ldcs((const unsigned*)(g_maskT + ((size_t)b * Nn + gi) * Nn + jq * 4));
        cp_async_wait0();
        __syncthreads();
        phaseA(0, buf0, mw);
        __syncthreads();
    }

    // ---- pipelined main loop (32 tiles of 32 j) ----
    for (int jt = 0; jt < 32; jt++) {
        char* bufN = smc + SB_BUF0 + ((jt + 1) & 1) * BUF_STR;
        const uint32_t bufN_sm = smem_base + SB_BUF0 + ((jt + 1) & 1) * BUF_STR;
        const uint32_t bufC_sm = smem_base + SB_BUF0 + (jt & 1) * BUF_STR;
        const bool has_next = (jt < 31);

        unsigned mw = 0;
        if (has_next) {
            cp_u(jt + 1);                    // group 1 (older)
            cp_v(jt + 1, bufN_sm);           // group 2
            mw = __ldcs((const unsigned*)(g_maskT + ((size_t)b * Nn + gi) * Nn +
                                          (jt + 1) * 32 + jq * 4));
        }

        // phase B: MMA from current buffer (overlaps both cp.async groups)
#pragma unroll
        for (int ks = 0; ks < 2; ks++) {
            uint32_t aAddr = bufC_sm + BA_OFF + h_b * A_HSTR + a_lm_row * A_RSTR +
                             ks * 32 + a_lm_kh * 16;
            uint32_t ah0, ah1, ah2, ah3, al0, al1, al2, al3;
            ldmatrix_x4(ah0, ah1, ah2, ah3, aAddr);
            ldmatrix_x4(al0, al1, al2, al3, aAddr + 64);
#pragma unroll
            for (int np = 0; np < 4; np++) {
                uint32_t bAddr = bufC_sm + BVH_OFF +
                                 (ks * 16 + b_lm_krow) * V_RSTR +
                                 (b_lm_ncol + np * 16) * 2;
                uint32_t bh0, bh1, bh2, bh3, bl0, bl1, bl2, bl3;
                ldmatrix_x4_trans(bh0, bh1, bh2, bh3, bAddr);
                ldmatrix_x4_trans(bl0, bl1, bl2, bl3, bAddr + (BVL_OFF - BVH_OFF));
                float* c0 = c[np * 2];
                float* c1 = c[np * 2 + 1];
                mma_bf16(c0, ah0, ah1, ah2, ah3, bh0, bh1);
                mma_bf16(c0, ah0, ah1, ah2, ah3, bl0, bl1);
                mma_bf16(c0, al0, al1, al2, al3, bh0, bh1);
                mma_bf16(c1, ah0, ah1, ah2, ah3, bh2, bh3);
                mma_bf16(c1, ah0, ah1, ah2, ah3, bl2, bl3);
                mma_bf16(c1, al0, al1, al2, al3, bh2, bh3);
            }
        }

        if (has_next) {
            cp_async_wait1();                // u group done; V group may still fly
            // u(k+1) written by this thread is read only by this thread -> no barrier needed
            phaseA(jt + 1, bufN, mw);
            cp_async_wait0();                // V(k+1) done
        }
        __syncthreads();
    }

    // ---- epilogue ----
    {
        int r = lane >> 2, cq = lane & 3;
        int go0 = i0 + ig * 16 + r;
        int go1 = go0 + 8;
#pragma unroll
        for (int nf = 0; nf < 8; nf++) {
            int col = h_b * 64 + nf * 8 + cq * 2;
            uint32_t h0 = cvt_bf16x2(c[nf][1], c[nf][0]);
            float e0 = __uint_as_float(h0 << 16), e1 = __uint_as_float(h0 & 0xFFFF0000u);
            uint32_t l0 = cvt_bf16x2(c[nf][1] - e1, c[nf][0] - e0);
            uint32_t h1 = cvt_bf16x2(c[nf][3], c[nf][2]);
            float e2 = __uint_as_float(h1 << 16), e3 = __uint_as_float(h1 & 0xFFFF0000u);
            uint32_t l1 = cvt_bf16x2(c[nf][3] - e3, c[nf][2] - e2);
            ((uint32_t*)g_op_hi)[(((size_t)b * Nn + go0) * Ee + col) >> 1] = h0;
            ((uint32_t*)g_op_lo)[(((size_t)b * Nn + go0) * Ee + col) >> 1] = l0;
            ((uint32_t*)g_op_hi)[(((size_t)b * Nn + go1) * Ee + col) >> 1] = h1;
            ((uint32_t*)g_op_lo)[(((size_t)b * Nn + go1) * Ee + col) >> 1] = l1;
        }
    }
}

// ---------------- launch ----------------
extern "C" void kernel_launch(void* const* d_in, const int* in_sizes, int n_in,
                              void* d_out, int out_size) {
    const float* x     = (const float*)d_in[0];
    const float* u     = (const float*)d_in[1];
    const void*  umask = d_in[2];
    const float* v_w   = (const float*)d_in[3];
    const float* out_w = (const float*)d_in[4];
    const float* u_w   = (const float*)d_in[5];
    const float* u_b   = (const float*)d_in[6];
    const float* lq    = (const float*)d_in[7];
    const float* lk    = (const float*)d_in[8];

    float* out = (float*)d_out;
    const size_t OUT_ELEMS  = (size_t)Bb * Nn * Ee;
    const size_t ATTN_ELEMS = (size_t)Bb * Hh * Nn * Nn;
    float* attn_out  = out + OUT_ELEMS;
    float* beta_slot = out + OUT_ELEMS + ATTN_ELEMS;

    static bool attr_set = false;
    if (!attr_set) {
        cudaFuncSetAttribute(fused_kernel, cudaFuncAttributeMaxDynamicSharedMemorySize, SB_TOT);
        attr_set = true;
    }

    detect_beta_kernel<<<1, 256>>>((const unsigned char*)umask, lq, lk, beta_slot);  // #1
    prep_kernel<<<PREP_GRID, 256>>>(umask, x, v_w, out_w);                            // #2
    gemm1_stats_kernel<<<512 + Nn * Bb, 256>>>(u, u_w, u_b);                          // #3
    fused_kernel<<<dim3(16, 8), 512, SB_TOT>>>(u, u_w, u_b, attn_out);                // #4 (profiled)
    gemm0_kernel<<<dim3(128, 4), 256>>>(out);                                         // #5
    (void)in_sizes; (void)n_in; (void)out_size;
}

// round 15
// speedup vs baseline: 1.2369x; 1.0878x over previous
#include <cuda_runtime.h>
#include <cuda_bf16.h>
#include <math.h>
#include <stdint.h>

#define Bb 8
#define Nn 1024
#define Ee 256
#define Hh 4
#define Uu 6
#define Oo 8
#define LAMBDA_INIT 0.63212055882855767840f
#define LOG2E 1.44269504088896340736f

typedef unsigned long long ull;

// ---------------- scratch (static device memory; no allocation) ----------------
__device__ unsigned char g_maskT[(size_t)Bb * Nn * Nn];
__device__ __nv_bfloat16 g_v_hi[(size_t)Bb * Nn * Ee];
__device__ __nv_bfloat16 g_v_lo[(size_t)Bb * Nn * Ee];
__device__ __nv_bfloat16 g_x_hi[(size_t)Bb * Nn * Ee];
__device__ __nv_bfloat16 g_x_lo[(size_t)Bb * Nn * Ee];
__device__ __nv_bfloat16 g_op_hi[(size_t)Bb * Nn * Ee];
__device__ __nv_bfloat16 g_op_lo[(size_t)Bb * Nn * Ee];
__device__ __nv_bfloat16 g_vw_hi[(size_t)Ee * Ee];
__device__ __nv_bfloat16 g_vw_lo[(size_t)Ee * Ee];
__device__ __nv_bfloat16 g_ow_hi[(size_t)Ee * Ee];
__device__ __nv_bfloat16 g_ow_lo[(size_t)Ee * Ee];
__device__ __nv_bfloat16 g_a_hi[(size_t)Bb * Hh * Nn * Nn];   // 64 MB attn bf16 hi
__device__ __nv_bfloat16 g_a_lo[(size_t)Bb * Hh * Nn * Nn];   // 64 MB attn bf16 lo
__device__ float g_beta;
__device__ int   g_mask_kind;

// ---------------- helpers ----------------
__device__ __forceinline__ ull pack2(float a, float b) {
    ull r; asm("mov.b64 %0, {%1,%2};" : "=l"(r) : "f"(a), "f"(b)); return r;
}
__device__ __forceinline__ float2 unpack2(ull v) {
    float2 r; asm("mov.b64 {%0,%1}, %2;" : "=f"(r.x), "=f"(r.y) : "l"(v)); return r;
}
__device__ __forceinline__ ull ffma2(ull a, ull b, ull c) {
    ull d; asm("fma.rn.f32x2 %0, %1, %2, %3;" : "=l"(d) : "l"(a), "l"(b), "l"(c)); return d;
}
__device__ __forceinline__ uint32_t cvt_bf16x2(float a1, float a0) {
    uint32_t r; asm("cvt.rn.bf16x2.f32 %0, %1, %2;" : "=r"(r) : "f"(a1), "f"(a0)); return r;
}
__device__ __forceinline__ float ex2f(float x) {
    float r; asm("ex2.approx.f32 %0, %1;" : "=f"(r) : "f"(x)); return r;
}
__device__ __forceinline__ uint32_t smem_u32(const void* p) {
    uint32_t a;
    asm("{ .reg .u64 t; cvta.to.shared.u64 t, %1; cvt.u32.u64 %0, t; }" : "=r"(a) : "l"(p));
    return a;
}
__device__ __forceinline__ void cp_async16(uint32_t smem_addr, const void* gmem) {
    asm volatile("cp.async.cg.shared.global [%0], [%1], 16;" :: "r"(smem_addr), "l"(gmem));
}
__device__ __forceinline__ void cp_async_commit() {
    asm volatile("cp.async.commit_group;" ::: "memory");
}
__device__ __forceinline__ void cp_async_wait0() {
    asm volatile("cp.async.wait_group 0;" ::: "memory");
}
__device__ __forceinline__ void ldmatrix_x4(uint32_t& r0, uint32_t& r1, uint32_t& r2,
                                            uint32_t& r3, uint32_t addr) {
    asm volatile("ldmatrix.sync.aligned.m8n8.x4.shared.b16 {%0,%1,%2,%3}, [%4];"
                 : "=r"(r0), "=r"(r1), "=r"(r2), "=r"(r3) : "r"(addr));
}
__device__ __forceinline__ void ldmatrix_x4_trans(uint32_t& r0, uint32_t& r1, uint32_t& r2,
                                                  uint32_t& r3, uint32_t addr) {
    asm volatile("ldmatrix.sync.aligned.m8n8.x4.trans.shared.b16 {%0,%1,%2,%3}, [%4];"
                 : "=r"(r0), "=r"(r1), "=r"(r2), "=r"(r3) : "r"(addr));
}
__device__ __forceinline__ void mma_bf16(float* c, uint32_t a0, uint32_t a1, uint32_t a2,
                                         uint32_t a3, uint32_t b0, uint32_t b1) {
    asm volatile(
        "mma.sync.aligned.m16n8k16.row.col.f32.bf16.bf16.f32 "
        "{%0,%1,%2,%3}, {%4,%5,%6,%7}, {%8,%9}, {%0,%1,%2,%3};"
        : "+f"(c[0]), "+f"(c[1]), "+f"(c[2]), "+f"(c[3])
        : "r"(a0), "r"(a1), "r"(a2), "r"(a3), "r"(b0), "r"(b1));
}

// ---------------- L1: detect mask dtype + beta ----------------
__global__ void detect_beta_kernel(const unsigned char* __restrict__ raw,
                                   const float* __restrict__ lq,
                                   const float* __restrict__ lk,
                                   float* __restrict__ beta_slot) {
    __shared__ int cnt[4];
    __shared__ float red[128];
    int t = threadIdx.x;
    if (t < 4) cnt[t] = 0;
    if (t < 128) red[t] = (t < 100) ? lq[t] * lk[t] : 0.f;
    __syncthreads();
    for (int i = t; i < 16384; i += blockDim.x)
        if (raw[i]) atomicAdd(&cnt[i & 3], 1);
    for (int st = 64; st > 0; st >>= 1) {
        if (t < st) red[t] += red[t + st];
        __syncthreads();
    }
    if (t == 0) {
        int kind;
        if (cnt[1] == 0 && cnt[2] == 0 && cnt[3] == 0) kind = 1;
        else if (cnt[0] == 0 && cnt[1] == 0)           kind = 2;
        else                                            kind = 0;
        g_mask_kind = kind;
        float lam1 = expf(red[0]);
        float beta = 1.f / (1.f + expf(-lam1 * LAMBDA_INIT));
        g_beta = beta;
        *beta_slot = beta;
    }
}

// ---------------- L2: prep = mask transpose + splits ----------------
#define NX4 ((int)((size_t)Bb * Nn * Ee / 4))
#define NW4 (Ee * Ee / 4)
#define PREP_GRID (8192 + (NX4 + 2 * NW4) / 256)

__global__ __launch_bounds__(256) void prep_kernel(const void* __restrict__ rawv,
                                                   const float* __restrict__ x,
                                                   const float* __restrict__ vw,
                                                   const float* __restrict__ ow) {
    int bid = blockIdx.x;
    if (bid < 8192) {
        __shared__ unsigned char tile[32][33];
        int xt = bid & 31, yt = (bid >> 5) & 31, b = bid >> 10;
        int i0 = xt * 32, j0 = yt * 32;
        int tx = threadIdx.x & 31, ty0 = threadIdx.x >> 5;
        int kind = g_mask_kind;
#pragma unroll
        for (int k = 0; k < 4; k++) {
            int ty = ty0 + k * 8;
            size_t src = ((size_t)b * Nn + (j0 + ty)) * Nn + (i0 + tx);
            unsigned char v;
            if (kind == 0)      v = (((const unsigned char*)rawv)[src] != 0);
            else if (kind == 1) v = (((const int*)rawv)[src] != 0);
            else                v = (((const float*)rawv)[src] != 0.f);
            tile[ty][tx] = v;
        }
        __syncthreads();
#pragma unroll
        for (int k = 0; k < 4; k++) {
            int ty = ty0 + k * 8;
            g_maskT[((size_t)b * Nn + (i0 + ty)) * Nn + (j0 + tx)] = tile[tx][ty];
        }
    } else {
        int idx = (bid - 8192) * 256 + threadIdx.x;
        const float* src;
        uint2 *hid, *lod;
        int li;
        if (idx < NX4) {
            src = x; hid = (uint2*)g_x_hi; lod = (uint2*)g_x_lo; li = idx;
        } else if (idx < NX4 + NW4) {
            src = vw; hid = (uint2*)g_vw_hi; lod = (uint2*)g_vw_lo; li = idx - NX4;
        } else {
            src = ow; hid = (uint2*)g_ow_hi; lod = (uint2*)g_ow_lo; li = idx - NX4 - NW4;
        }
        float4 v = ((const float4*)src)[li];
        uint32_t h0 = cvt_bf16x2(v.y, v.x);
        uint32_t h1 = cvt_bf16x2(v.w, v.z);
        float a0 = __uint_as_float(h0 << 16), a1 = __uint_as_float(h0 & 0xFFFF0000u);
        float a2 = __uint_as_float(h1 << 16), a3 = __uint_as_float(h1 & 0xFFFF0000u);
        uint32_t l0 = cvt_bf16x2(v.y - a1, v.x - a0);
        uint32_t l1 = cvt_bf16x2(v.w - a3, v.z - a2);
        hid[li] = make_uint2(h0, h1);
        lod[li] = make_uint2(l0, l1);
    }
}

// ---------------- gemm body (HMMA, 64x64 tile, 3 hi/lo combos) ----------------
#define GR_STR 144
#define GEMM_SMEM (4 * 64 * GR_STR)
template <int MODE>
__device__ __forceinline__ void gemm_body(
    char* sm, int bx, int by,
    const __nv_bfloat16* __restrict__ Ahi, const __nv_bfloat16* __restrict__ Alo,
    const __nv_bfloat16* __restrict__ Whi, const __nv_bfloat16* __restrict__ Wlo,
    float* __restrict__ Y, __nv_bfloat16* __restrict__ Yhi, __nv_bfloat16* __restrict__ Ylo) {
    char* sAh = sm;
    char* sAl = sm + 64 * GR_STR;
    char* sWh = sm + 2 * 64 * GR_STR;
    char* sWl = sm + 3 * 64 * GR_STR;
    const uint32_t smb = smem_u32(sm);

    const int t = threadIdx.x;
    const int wid = t >> 5, lane = t & 31;
    const int row0 = bx * 64;
    const int col0 = by * 64;
    const int mw = wid >> 1, nw = wid & 1;
    const int lr = lane & 7, quad = lane >> 3;
    const uint32_t aRow = (uint32_t)(mw * 16 + (quad & 1) * 8 + lr);
    const uint32_t aKoff = (uint32_t)((quad >> 1) * 16);
    const uint32_t bRow = (uint32_t)((quad >> 1) * 8 + lr);
    const uint32_t bKoff = (uint32_t)((quad & 1) * 16);

    float c[4][4];
#pragma unroll
    for (int nf = 0; nf < 4; nf++)
#pragma unroll
        for (int k = 0; k < 4; k++) c[nf][k] = 0.f;

    for (int kc = 0; kc < 4; kc++) {
        __syncthreads();
#pragma unroll
        for (int q = 0; q < 2; q++) {
            int idx = t + q * 256;
            int r = idx >> 3, c16 = idx & 7;
            *(uint4*)(sAh + r * GR_STR + c16 * 16) =
                ((const uint4*)(Ahi + (size_t)(row0 + r) * Ee + kc * 64))[c16];
            *(uint4*)(sAl + r * GR_STR + c16 * 16) =
                ((const uint4*)(Alo + (size_t)(row0 + r) * Ee + kc * 64))[c16];
            *(uint4*)(sWh + r * GR_STR + c16 * 16) =
                ((const uint4*)(Whi + (size_t)(col0 + r) * Ee + kc * 64))[c16];
            *(uint4*)(sWl + r * GR_STR + c16 * 16) =
                ((const uint4*)(Wlo + (size_t)(col0 + r) * Ee + kc * 64))[c16];
        }
        __syncthreads();
#pragma unroll
        for (int ks = 0; ks < 4; ks++) {
            uint32_t aBase = smb + aRow * GR_STR + ks * 32 + aKoff;
            uint32_t ah0, ah1, ah2, ah3, al0, al1, al2, al3;
            ldmatrix_x4(ah0, ah1, ah2, ah3, aBase);
            ldmatrix_x4(al0, al1, al2, al3, aBase + 64 * GR_STR);
#pragma unroll
            for (int np = 0; np < 2; np++) {
                uint32_t bBase = smb + 2 * 64 * GR_STR +
                                 (nw * 32 + np * 16 + bRow) * GR_STR + ks * 32 + bKoff;
                uint32_t bh0, bh1, bh2, bh3, bl0, bl1, bl2, bl3;
                ldmatrix_x4(bh0, bh1, bh2, bh3, bBase);
                ldmatrix_x4(bl0, bl1, bl2, bl3, bBase + 64 * GR_STR);
                float* c0 = c[np * 2];
                float* c1 = c[np * 2 + 1];
                mma_bf16(c0, ah0, ah1, ah2, ah3, bh0, bh1);
                mma_bf16(c0, ah0, ah1, ah2, ah3, bl0, bl1);
                mma_bf16(c0, al0, al1, al2, al3, bh0, bh1);
                mma_bf16(c1, ah0, ah1, ah2, ah3, bh2, bh3);
                mma_bf16(c1, ah0, ah1, ah2, ah3, bl2, bl3);
                mma_bf16(c1, al0, al1, al2, al3, bh2, bh3);
            }
        }
    }

    int r0 = row0 + mw * 16 + (lane >> 2);
    int colb = col0 + nw * 32 + (lane & 3) * 2;
#pragma unroll
    for (int nf = 0; nf < 4; nf++) {
        int col = colb + nf * 8;
        if (MODE == 0) {
            *(float2*)(Y + (size_t)r0 * Ee + col) = make_float2(c[nf][0], c[nf][1]);
            *(float2*)(Y + (size_t)(r0 + 8) * Ee + col) = make_float2(c[nf][2], c[nf][3]);
        } else {
            uint32_t h0 = cvt_bf16x2(c[nf][1], c[nf][0]);
            float e0 = __uint_as_float(h0 << 16), e1 = __uint_as_float(h0 & 0xFFFF0000u);
            uint32_t l0 = cvt_bf16x2(c[nf][1] - e1, c[nf][0] - e0);
            uint32_t h1 = cvt_bf16x2(c[nf][3], c[nf][2]);
            float e2 = __uint_as_float(h1 << 16), e3 = __uint_as_float(h1 & 0xFFFF0000u);
            uint32_t l1 = cvt_bf16x2(c[nf][3] - e3, c[nf][2] - e2);
            ((uint32_t*)Yhi)[((size_t)r0 * Ee + col) >> 1] = h0;
            ((uint32_t*)Ylo)[((size_t)r0 * Ee + col) >> 1] = l0;
            ((uint32_t*)Yhi)[((size_t)(r0 + 8) * Ee + col) >> 1] = h1;
            ((uint32_t*)Ylo)[((size_t)(r0 + 8) * Ee + col) >> 1] = l1;
        }
    }
}

// ---------------- stats2 body: scores once -> l -> attn fp32 + A bf16 hi/lo ----------------
__device__ __forceinline__ void stats2_body(char* sm, int i, int b,
                                            const float* __restrict__ u,
                                            const float* __restrict__ u_w,
                                            const float* __restrict__ u_b,
                                            float* __restrict__ attn_out) {
    ull* s_w2 = (ull*)sm;                   // 48 ull
    ull* s_b2 = (ull*)(sm + 384);           // 8 ull
    float* s_red = (float*)(sm + 448);      // 8x9
    float* s_l = (float*)(sm + 448 + 288);  // 8
    int t = threadIdx.x;
    if (t < 48) { float w = u_w[t] * LOG2E; s_w2[t] = pack2(w, w); }
    if (t < 8)  { float bb = u_b[t] * LOG2E; s_b2[t] = pack2(bb, bb); }
    __syncthreads();

    int j0 = t * 4;
    unsigned mword = *(const unsigned*)(g_maskT + ((size_t)b * Nn + i) * Nn + j0);
    bool m0 = (mword & 0xFFu) != 0, m1 = ((mword >> 8) & 0xFFu) != 0;
    bool m2 = ((mword >> 16) & 0xFFu) != 0, m3 = ((mword >> 24) & 0xFFu) != 0;

    ulonglong2 u2[Uu];
#pragma unroll
    for (int c = 0; c < Uu; c++)
        u2[c] = __ldcs((const ulonglong2*)(u + ((size_t)(b * Uu + c) * Nn + i) * Nn + j0));

    // exps computed ONCE, kept in regs
    float e[Oo][4];
    float l[Oo];
#pragma unroll
    for (int o = 0; o < Oo; o++) {
        ull sa = s_b2[o], sb = s_b2[o];
#pragma unroll
        for (int c = 0; c < Uu; c++) {
            sa = ffma2(s_w2[o * Uu + c], u2[c].x, sa);
            sb = ffma2(s_w2[o * Uu + c], u2[c].y, sb);
        }
        float2 f0 = unpack2(sa), f1 = unpack2(sb);
        e[o][0] = m0 ? 0.f : ex2f(f0.x);
        e[o][1] = m1 ? 0.f : ex2f(f0.y);
        e[o][2] = m2 ? 0.f : ex2f(f1.x);
        e[o][3] = m3 ? 0.f : ex2f(f1.y);
        l[o] = (e[o][0] + e[o][1]) + (e[o][2] + e[o][3]);
    }
#pragma unroll
    for (int o = 0; o < Oo; o++)
#pragma unroll
        for (int st = 16; st > 0; st >>= 1)
            l[o] += __shfl_xor_sync(0xFFFFFFFFu, l[o], st);
    int w = t >> 5, lane = t & 31;
    if (lane == 0) {
#pragma unroll
        for (int o = 0; o < Oo; o++) s_red[o * 9 + w] = l[o];
    }
    __syncthreads();
    if (t < 8) {
        float s = 0.f;
#pragma unroll
        for (int w2 = 0; w2 < 8; w2++) s += s_red[t * 9 + w2];
        s_l[t] = 1.0f / s;
    }
    __syncthreads();

    const float beta = g_beta;
#pragma unroll
    for (int h = 0; h < Hh; h++) {
        float rl0 = s_l[2 * h], rl1 = s_l[2 * h + 1];
        float a0 = e[2 * h][0] * rl0 - beta * e[2 * h + 1][0] * rl1;
        float a1 = e[2 * h][1] * rl0 - beta * e[2 * h + 1][1] * rl1;
        float a2 = e[2 * h][2] * rl0 - beta * e[2 * h + 1][2] * rl1;
        float a3 = e[2 * h][3] * rl0 - beta * e[2 * h + 1][3] * rl1;
        size_t base = ((size_t)(b * Hh + h) * Nn + i) * Nn + j0;
        __stcs((float4*)(attn_out + base), make_float4(a0, a1, a2, a3));
        uint32_t hA = cvt_bf16x2(a1, a0);
        uint32_t hB = cvt_bf16x2(a3, a2);
        float e0 = __uint_as_float(hA << 16);
        float e1 = __uint_as_float(hA & 0xFFFF0000u);
        float e2 = __uint_as_float(hB << 16);
        float e3 = __uint_as_float(hB & 0xFFFF0000u);
        uint32_t lA = cvt_bf16x2(a1 - e1, a0 - e0);
        uint32_t lB = cvt_bf16x2(a3 - e3, a2 - e2);
        __stcs((uint2*)((uint32_t*)g_a_hi + (base >> 1)), make_uint2(hA, hB));
        __stcs((uint2*)((uint32_t*)g_a_lo + (base >> 1)), make_uint2(lA, lB));
    }
}

// ---------------- L3: gemm<1> (blocks [0,512)) + stats2 (blocks [512, 8704)) ----------------
__global__ __launch_bounds__(256) void gemm1_stats_kernel(const float* __restrict__ u,
                                                          const float* __restrict__ u_w,
                                                          const float* __restrict__ u_b,
                                                          float* __restrict__ attn_out) {
    __shared__ __align__(16) char sm[GEMM_SMEM];
    int bid = blockIdx.x;
    if (bid < 512) {
        gemm_body<1>(sm, bid & 127, bid >> 7,
                     g_x_hi, g_x_lo, g_vw_hi, g_vw_lo, nullptr, g_v_hi, g_v_lo);
    } else {
        int sid = bid - 512;
        stats2_body(sm, sid & 1023, sid >> 10, u, u_w, u_b, attn_out);
    }
}

// ---------------- L5: out projection ----------------
__global__ __launch_bounds__(256) void gemm0_kernel(float* __restrict__ Y) {
    __shared__ __align__(16) char sm[GEMM_SMEM];
    gemm_body<0>(sm, blockIdx.x, blockIdx.y,
                 g_op_hi, g_op_lo, g_ow_hi, g_ow_lo, Y, nullptr, nullptr);
}

// ---------------- L4: av — pure HMMA GEMM: op[b,i,h*64+d] = sum_j A[b,h,i,j] V[b,j,h*64+d] ----------------
// grid (8 i-strips, 32 bh), 256 threads (8 warps x 16 rows), j tiles of 64, double buffered.
#define AV_RS   144
#define AV_AH   0
#define AV_AL   18432          // 128 x 144
#define AV_VH   36864
#define AV_VL   46080          // +64 x 144
#define AV_BUF  55296
#define AV_TOT  (2 * 55296)    // 110592

__global__ __launch_bounds__(256) void av_kernel() {
    extern __shared__ char smc[];
    const uint32_t smem_base = smem_u32(smc);

    const int t = threadIdx.x;
    const int wid = t >> 5;
    const int lane = t & 31;
    const int i0 = blockIdx.x * 128;
    const int bh = blockIdx.y;
    const int b = bh >> 2, h = bh & 3;

    const __nv_bfloat16* Ahg = g_a_hi + ((size_t)bh * Nn + i0) * Nn;
    const __nv_bfloat16* Alg = g_a_lo + ((size_t)bh * Nn + i0) * Nn;
    const __nv_bfloat16* Vhg = g_v_hi + (size_t)b * Nn * Ee + h * 64;
    const __nv_bfloat16* Vlg = g_v_lo + (size_t)b * Nn * Ee + h * 64;

    const int lg = lane >> 3, lr = lane & 7;
    const uint32_t a_row = (uint32_t)(wid * 16 + (lg & 1) * 8 + lr);
    const uint32_t a_kh = (uint32_t)(lg >> 1);
    const uint32_t b_krow = (uint32_t)((lg & 1) * 8 + lr);
    const uint32_t b_ncol = (uint32_t)((lg >> 1) * 8);

    float c[8][4];
#pragma unroll
    for (int nf = 0; nf < 8; nf++)
#pragma unroll
        for (int k = 0; k < 4; k++) c[nf][k] = 0.f;

    auto cp_tile = [&](int jt, uint32_t buf) {
        // A hi/lo: 128 rows x 8 chunks each
#pragma unroll
        for (int q = 0; q < 4; q++) {
            int idx = t + q * 256;
            int r = idx >> 3, ck = idx & 7;
            cp_async16(buf + AV_AH + r * AV_RS + ck * 16,
                       Ahg + (size_t)r * Nn + jt * 64 + ck * 8);
            cp_async16(buf + AV_AL + r * AV_RS + ck * 16,
                       Alg + (size_t)r * Nn + jt * 64 + ck * 8);
        }
        // V hi/lo: 64 rows x 8 chunks each
#pragma unroll
        for (int q = 0; q < 2; q++) {
            int idx = t + q * 256;
            int r = idx >> 3, ck = idx & 7;
            cp_async16(buf + AV_VH + r * AV_RS + ck * 16,
                       Vhg + (size_t)(jt * 64 + r) * Ee + ck * 8);
            cp_async16(buf + AV_VL + r * AV_RS + ck * 16,
                       Vlg + (size_t)(jt * 64 + r) * Ee + ck * 8);
        }
        cp_async_commit();
    };

    // prologue
    cp_tile(0, smem_base);
    cp_async_wait0();
    __syncthreads();

    for (int jt = 0; jt < 16; jt++) {
        const uint32_t bufC = smem_base + (jt & 1) * AV_BUF;
        const bool has_next = (jt < 15);
        if (has_next) cp_tile(jt + 1, smem_base + ((jt + 1) & 1) * AV_BUF);

#pragma unroll
        for (int ks = 0; ks < 4; ks++) {
            uint32_t aAddr = bufC + AV_AH + a_row * AV_RS + ks * 32 + a_kh * 16;
            uint32_t ah0, ah1, ah2, ah3, al0, al1, al2, al3;
            ldmatrix_x4(ah0, ah1, ah2, ah3, aAddr);
            ldmatrix_x4(al0, al1, al2, al3, aAddr + (AV_AL - AV_AH));
#pragma unroll
            for (int np = 0; np < 4; np++) {
                uint32_t bAddr = bufC + AV_VH + (ks * 16 + b_krow) * AV_RS +
                                 (np * 16 + b_ncol) * 2;
                uint32_t bh0, bh1, bh2, bh3, bl0, bl1, bl2, bl3;
                ldmatrix_x4_trans(bh0, bh1, bh2, bh3, bAddr);
                ldmatrix_x4_trans(bl0, bl1, bl2, bl3, bAddr + (AV_VL - AV_VH));
                float* c0 = c[np * 2];
                float* c1 = c[np * 2 + 1];
                mma_bf16(c0, ah0, ah1, ah2, ah3, bh0, bh1);
                mma_bf16(c0, ah0, ah1, ah2, ah3, bl0, bl1);
                mma_bf16(c0, al0, al1, al2, al3, bh0, bh1);
                mma_bf16(c1, ah0, ah1, ah2, ah3, bh2, bh3);
                mma_bf16(c1, ah0, ah1, ah2, ah3, bl2, bl3);
                mma_bf16(c1, al0, al1, al2, al3, bh2, bh3);
            }
        }

        if (has_next) cp_async_wait0();
        __syncthreads();
    }

    // epilogue: C -> g_op bf16 hi/lo
    {
        int r = lane >> 2, cq = lane & 3;
        int go0 = i0 + wid * 16 + r;
        int go1 = go0 + 8;
#pragma unroll
        for (int nf = 0; nf < 8; nf++) {
            int col = h * 64 + nf * 8 + cq * 2;
            uint32_t h0 = cvt_bf16x2(c[nf][1], c[nf][0]);
            float e0 = __uint_as_float(h0 << 16), e1 = __uint_as_float(h0 & 0xFFFF0000u);
            uint32_t l0 = cvt_bf16x2(c[nf][1] - e1, c[nf][0] - e0);
            uint32_t h1 = cvt_bf16x2(c[nf][3], c[nf][2]);
            float e2 = __uint_as_float(h1 << 16), e3 = __uint_as_float(h1 & 0xFFFF0000u);
            uint32_t l1 = cvt_bf16x2(c[nf][3] - e3, c[nf][2] - e2);
            ((uint32_t*)g_op_hi)[(((size_t)b * Nn + go0) * Ee + col) >> 1] = h0;
            ((uint32_t*)g_op_lo)[(((size_t)b * Nn + go0) * Ee + col) >> 1] = l0;
            ((uint32_t*)g_op_hi)[(((size_t)b * Nn + go1) * Ee + col) >> 1] = h1;
            ((uint32_t*)g_op_lo)[(((size_t)b * Nn + go1) * Ee + col) >> 1] = l1;
        }
    }
}

// ---------------- launch ----------------
extern "C" void kernel_launch(void* const* d_in, const int* in_sizes, int n_in,
                              void* d_out, int out_size) {
    const float* x     = (const float*)d_in[0];
    const float* u     = (const float*)d_in[1];
    const void*  umask = d_in[2];
    const float* v_w   = (const float*)d_in[3];
    const float* out_w = (const float*)d_in[4];
    const float* u_w   = (const float*)d_in[5];
    const float* u_b   = (const float*)d_in[6];
    const float* lq    = (const float*)d_in[7];
    const float* lk    = (const float*)d_in[8];

    float* out = (float*)d_out;
    const size_t OUT_ELEMS  = (size_t)Bb * Nn * Ee;
    const size_t ATTN_ELEMS = (size_t)Bb * Hh * Nn * Nn;
    float* attn_out  = out + OUT_ELEMS;
    float* beta_slot = out + OUT_ELEMS + ATTN_ELEMS;

    static bool attr_set = false;
    if (!attr_set) {
        cudaFuncSetAttribute(av_kernel, cudaFuncAttributeMaxDynamicSharedMemorySize, AV_TOT);
        attr_set = true;
    }

    detect_beta_kernel<<<1, 256>>>((const unsigned char*)umask, lq, lk, beta_slot);   // #1
    prep_kernel<<<PREP_GRID, 256>>>(umask, x, v_w, out_w);                             // #2
    gemm1_stats_kernel<<<512 + Nn * Bb, 256>>>(u, u_w, u_b, attn_out);                 // #3
    av_kernel<<<dim3(8, 32), 256, AV_TOT>>>();                                         // #4 (profiled)
    gemm0_kernel<<<dim3(128, 4), 256>>>(out);                                          // #5
    (void)in_sizes; (void)n_in; (void)out_size;
}